// round 9
// baseline (speedup 1.0000x reference)
#include <cuda_runtime.h>
#include <math.h>
#include <stdint.h>

#define TOTAL   5120
#define DIMM    1024
#define NH      16
#define HDD     64
#define NB      4
#define MAXLEN  2048
#define NQKV    3072

// Scratch (device globals: no allocation allowed)
__device__ float g_qkv[(size_t)TOTAL * NQKV];    // q|k|v (tf32 values)
__device__ float g_attn[(size_t)TOTAL * DIMM];   // attention out (tf32 values)
__device__ float g_a [(size_t)TOTAL * DIMM];     // hs rounded to tf32
__device__ float g_w1[(size_t)NQKV * DIMM];      // Wqkv rounded to tf32
__device__ float g_w2[(size_t)DIMM * DIMM];      // Wo rounded to tf32
__device__ int   g_flag;                         // 1 => gemm_v2 bad, use fallback

extern __shared__ __align__(1024) uint8_t dynraw[];

__device__ __forceinline__ unsigned tf32r(float x) {
    unsigned u;
    asm("cvt.rna.tf32.f32 %0, %1;" : "=r"(u) : "f"(x));
    return u;
}
__device__ __forceinline__ float tf32rf(float x) {
    return __uint_as_float(tf32r(x));
}

#define MMA_TF32(acc, a0,a1,a2,a3, b0,b1)                                     \
    asm volatile("mma.sync.aligned.m16n8k8.row.col.f32.tf32.tf32.f32 "        \
                 "{%0,%1,%2,%3}, {%4,%5,%6,%7}, {%8,%9}, {%0,%1,%2,%3};"      \
                 : "+f"((acc)[0]), "+f"((acc)[1]), "+f"((acc)[2]), "+f"((acc)[3]) \
                 : "r"(a0), "r"(a1), "r"(a2), "r"(a3), "r"(b0), "r"(b1))

// ---------------------------------------------------------------------------
// Elementwise round-to-tf32 copy (vectorized).
// ---------------------------------------------------------------------------
__global__ void __launch_bounds__(256) cvt_tf32(const float* __restrict__ src,
                                                float* __restrict__ dst, int n4)
{
    int i = blockIdx.x * 256 + threadIdx.x;
    if (i >= n4) return;
    float4 v = ((const float4*)src)[i];
    v.x = tf32rf(v.x); v.y = tf32rf(v.y);
    v.z = tf32rf(v.z); v.w = tf32rf(v.w);
    ((float4*)dst)[i] = v;
}

// ---------------------------------------------------------------------------
// Flag + GEMM spot-check (4096 sampled dot products in fp32).
// ---------------------------------------------------------------------------
__global__ void zero_flag_kernel() { g_flag = 0; }

__global__ void __launch_bounds__(256) check_gemm(
    const float* __restrict__ A, const float* __restrict__ Bw,
    const float* __restrict__ C, int M, int N, int K)
{
    int s = blockIdx.x * 256 + threadIdx.x;
    int row = (int)(((unsigned)s * 2654435761u) % (unsigned)M);
    int col = (int)(((unsigned)s * 40503u + 17u) % (unsigned)N);
    const float* a = &A[(size_t)row * K];
    const float* b = &Bw[(size_t)col * K];
    float ref = 0.f;
    for (int k = 0; k < K; k += 4) {
        float4 av = *(const float4*)&a[k];
        float4 bv = *(const float4*)&b[k];
        ref += av.x * bv.x + av.y * bv.y + av.z * bv.z + av.w * bv.w;
    }
    float got = C[(size_t)row * N + col];
    if (fabsf(got - ref) > 1e-2f * (1.0f + fabsf(ref)))
        atomicOr(&g_flag, 1);
}

// ===========================================================================
// GEMM v2: mma.sync tf32 NT, CTA tile 128x256, 8 warps in 2x4 grid,
// warp tile 64x64 (1.0 LDS per MMA). cp.async double-buffered, chunk-XOR
// swizzle. Inputs pre-rounded tf32 (no cvt in inner loop).
// Smem per buffer: A 16KB + B 32KB = 48KB; two buffers = 96KB.
// ===========================================================================
__global__ void __launch_bounds__(256, 1) gemm_v2(
    const float* __restrict__ A, const float* __restrict__ Bw,
    float* __restrict__ C, int M, int N, int K, int round_out)
{
    const int tid  = threadIdx.x;
    const int lane = tid & 31, w = tid >> 5;
    const int g = lane >> 2, t = lane & 3;
    const int wm = w >> 2, wn = w & 3;           // 2 x 4 warp grid
    const int bm = blockIdx.y * 128, bn = blockIdx.x * 256;

    float acc[4][8][4] = {};                     // 128 accumulator regs

    const unsigned sbase = (unsigned)__cvta_generic_to_shared(dynraw);

#define V2_STAGE(buf, k0)                                                     \
    {                                                                         \
        unsigned base = sbase + (buf) * 49152u;                               \
        _Pragma("unroll")                                                     \
        for (int it = 0; it < 4; it++) {         /* A: 1024 chunks */         \
            int id = tid + 256 * it;                                          \
            int row = id >> 3, c = id & 7;                                    \
            unsigned off = base + (unsigned)(row * 32 + ((c ^ (row & 7)) << 2)) * 4; \
            asm volatile("cp.async.ca.shared.global [%0],[%1],16;\n"          \
                         :: "r"(off), "l"(&A[(size_t)(bm + row) * K + (k0) + c * 4])); \
        }                                                                     \
        _Pragma("unroll")                                                     \
        for (int it = 0; it < 8; it++) {         /* B: 2048 chunks */         \
            int id = tid + 256 * it;                                          \
            int row = id >> 3, c = id & 7;                                    \
            unsigned off = base + 16384u + (unsigned)(row * 32 + ((c ^ (row & 7)) << 2)) * 4; \
            asm volatile("cp.async.ca.shared.global [%0],[%1],16;\n"          \
                         :: "r"(off), "l"(&Bw[(size_t)(bn + row) * K + (k0) + c * 4])); \
        }                                                                     \
        asm volatile("cp.async.commit_group;\n");                             \
    }

    V2_STAGE(0, 0);
    int buf = 0;
    for (int k0 = 0; k0 < K; k0 += 32) {
        asm volatile("cp.async.wait_group 0;\n");
        __syncthreads();
        if (k0 + 32 < K) V2_STAGE(buf ^ 1, k0 + 32);

        const float* Ab = (const float*)(dynraw + buf * 49152);
        const float* Bb = (const float*)(dynraw + buf * 49152 + 16384);
#pragma unroll
        for (int o = 0; o < 4; o++) {
            const int c0 = ((2 * o) ^ g) << 2, c1 = ((2 * o + 1) ^ g) << 2;
            unsigned a[4][4], b[8][2];
#pragma unroll
            for (int mt = 0; mt < 4; mt++) {
                int r0 = wm * 64 + mt * 16 + g;
                a[mt][0] = __float_as_uint(Ab[ r0      * 32 + c0 + t]);
                a[mt][2] = __float_as_uint(Ab[ r0      * 32 + c1 + t]);
                a[mt][1] = __float_as_uint(Ab[(r0 + 8) * 32 + c0 + t]);
                a[mt][3] = __float_as_uint(Ab[(r0 + 8) * 32 + c1 + t]);
            }
#pragma unroll
            for (int nt = 0; nt < 8; nt++) {
                int rb = wn * 64 + nt * 8 + g;
                b[nt][0] = __float_as_uint(Bb[rb * 32 + c0 + t]);
                b[nt][1] = __float_as_uint(Bb[rb * 32 + c1 + t]);
            }
#pragma unroll
            for (int mt = 0; mt < 4; mt++)
#pragma unroll
                for (int nt = 0; nt < 8; nt++)
                    MMA_TF32(acc[mt][nt], a[mt][0], a[mt][1], a[mt][2], a[mt][3],
                             b[nt][0], b[nt][1]);
        }
        buf ^= 1;
    }

#pragma unroll
    for (int mt = 0; mt < 4; mt++) {
        int r = bm + wm * 64 + mt * 16 + g;
#pragma unroll
        for (int nt = 0; nt < 8; nt++) {
            int cn = bn + wn * 64 + nt * 8 + 2 * t;
            float v0 = acc[mt][nt][0], v1 = acc[mt][nt][1];
            float v2 = acc[mt][nt][2], v3 = acc[mt][nt][3];
            if (round_out) {
                v0 = tf32rf(v0); v1 = tf32rf(v1); v2 = tf32rf(v2); v3 = tf32rf(v3);
            }
            *(float2*)&C[(size_t)r * N + cn]       = make_float2(v0, v1);
            *(float2*)&C[(size_t)(r + 8) * N + cn] = make_float2(v2, v3);
        }
    }
}

// ===========================================================================
// Fallback: proven 128x128 mma.sync GEMM — runs only when g_flag != 0.
// ===========================================================================
__global__ void __launch_bounds__(256, 2) mma_gemm_nt(
    const float* __restrict__ A, const float* __restrict__ Bw,
    float* __restrict__ C, int M, int N, int K, int round_out)
{
    if (g_flag == 0) return;                     // gemm_v2 verified good

    float* As = (float*)dynraw;                  // [2][128*32]
    float* Bs = (float*)dynraw + 8192;

    const int tid  = threadIdx.x;
    const int lane = tid & 31, w = tid >> 5;
    const int g = lane >> 2, t = lane & 3;
    const int wm = w >> 2, wn = w & 3;
    const int bm = blockIdx.y * 128, bn = blockIdx.x * 128;

    float acc[4][4][4] = {};

    const unsigned sA0 = (unsigned)__cvta_generic_to_shared(As);
    const unsigned sB0 = (unsigned)__cvta_generic_to_shared(Bs);

#define GEMM_STAGE(buf, k0)                                                   \
    {                                                                         \
        unsigned sa = sA0 + (buf) * 16384, sb = sB0 + (buf) * 16384;          \
        _Pragma("unroll")                                                     \
        for (int it = 0; it < 4; it++) {                                      \
            int id = tid + 256 * it;                                          \
            int row = id >> 3, c = id & 7;                                    \
            unsigned off = (unsigned)(row * 32 + ((c ^ (row & 7)) << 2)) * 4; \
            asm volatile("cp.async.ca.shared.global [%0],[%1],16;\n"          \
                         :: "r"(sa + off), "l"(&A [(size_t)(bm + row) * K + (k0) + c * 4])); \
            asm volatile("cp.async.ca.shared.global [%0],[%1],16;\n"          \
                         :: "r"(sb + off), "l"(&Bw[(size_t)(bn + row) * K + (k0) + c * 4])); \
        }                                                                     \
        asm volatile("cp.async.commit_group;\n");                             \
    }

    GEMM_STAGE(0, 0);
    int buf = 0;
    for (int k0 = 0; k0 < K; k0 += 32) {
        asm volatile("cp.async.wait_group 0;\n");
        __syncthreads();
        if (k0 + 32 < K) GEMM_STAGE(buf ^ 1, k0 + 32);

        const float* Ab = As + buf * 4096;
        const float* Bb = Bs + buf * 4096;
#pragma unroll
        for (int o = 0; o < 4; o++) {
            const int c0 = ((2 * o) ^ g) << 2, c1 = ((2 * o + 1) ^ g) << 2;
            unsigned a[4][4], b[4][2];
#pragma unroll
            for (int mt = 0; mt < 4; mt++) {
                int r0 = wm * 64 + mt * 16 + g;
                a[mt][0] = __float_as_uint(Ab[ r0      * 32 + c0 + t]);
                a[mt][2] = __float_as_uint(Ab[ r0      * 32 + c1 + t]);
                a[mt][1] = __float_as_uint(Ab[(r0 + 8) * 32 + c0 + t]);
                a[mt][3] = __float_as_uint(Ab[(r0 + 8) * 32 + c1 + t]);
            }
#pragma unroll
            for (int nt = 0; nt < 4; nt++) {
                int r0 = wn * 32 + nt * 8 + g;
                b[nt][0] = __float_as_uint(Bb[r0 * 32 + c0 + t]);
                b[nt][1] = __float_as_uint(Bb[r0 * 32 + c1 + t]);
            }
#pragma unroll
            for (int mt = 0; mt < 4; mt++)
#pragma unroll
                for (int nt = 0; nt < 4; nt++)
                    MMA_TF32(acc[mt][nt], a[mt][0], a[mt][1], a[mt][2], a[mt][3],
                             b[nt][0], b[nt][1]);
        }
        buf ^= 1;
    }

#pragma unroll
    for (int mt = 0; mt < 4; mt++) {
        int r = bm + wm * 64 + mt * 16 + g;
#pragma unroll
        for (int nt = 0; nt < 4; nt++) {
            int cn = bn + wn * 32 + nt * 8 + 2 * t;
            float v0 = acc[mt][nt][0], v1 = acc[mt][nt][1];
            float v2 = acc[mt][nt][2], v3 = acc[mt][nt][3];
            if (round_out) {
                v0 = tf32rf(v0); v1 = tf32rf(v1); v2 = tf32rf(v2); v3 = tf32rf(v3);
            }
            *(float2*)&C[(size_t)r * N + cn]       = make_float2(v0, v1);
            *(float2*)&C[(size_t)(r + 8) * N + cn] = make_float2(v2, v3);
        }
    }
}

// ---------------------------------------------------------------------------
// RoPE in-place on q,k sections of g_qkv; outputs rounded to tf32.
// ---------------------------------------------------------------------------
__global__ void __launch_bounds__(256) rope_kernel(const int* __restrict__ cu)
{
    int tt = blockIdx.x * 256 + threadIdx.x;
    int j  = tt & 31;
    int hh = (tt >> 5) & 15;
    int s  = (tt >> 9) & 1;
    int r  = tt >> 10;
    if (r >= TOTAL) return;

    int b = 0;
#pragma unroll
    for (int i = 1; i < NB; i++) if (r >= cu[i]) b = i;
    int pos = r - cu[b];

    float inv = exp2f(-(float)j * (13.287712379549449f / 32.0f));
    float fr  = (float)pos * inv;
    float c, sn;
    sincosf(fr, &sn, &c);

    float* base = g_qkv + (size_t)r * NQKV + s * DIMM + hh * HDD;
    float x1 = base[j], x2 = base[j + 32];
    base[j]      = tf32rf(x1 * c - x2 * sn);
    base[j + 32] = tf32rf(x2 * c + x1 * sn);
}

// ---------------------------------------------------------------------------
// Tensor-core flash attention (tf32, mma.sync). g_qkv holds tf32 values so
// staging is pure copies (Q x 0.125 exact). K/V staged via cp.async.
// ---------------------------------------------------------------------------
__global__ void __launch_bounds__(256, 2) attn_kernel(const int* __restrict__ cu)
{
    float* Qs = (float*)dynraw;             // 128*64
    float* Ks = (float*)dynraw + 8192;      // 64*64
    float* Vs = (float*)dynraw + 12288;     // 64*64
    float* Ps = (float*)dynraw + 16384;     // 128*64

    const int tid  = threadIdx.x;
    const int lane = tid & 31, w = tid >> 5;
    const int g = lane >> 2, t = lane & 3;
    const int h  = blockIdx.y;
    const int qt = blockIdx.x * 128;

    const unsigned sK = (unsigned)__cvta_generic_to_shared(Ks);
    const unsigned sV = (unsigned)__cvta_generic_to_shared(Vs);

    int b = 0;
#pragma unroll
    for (int i = 1; i < NB; i++) if (qt >= cu[i]) b = i;
    const int base = cu[b];
    const int L    = cu[b + 1] - base;

#pragma unroll
    for (int it = 0; it < 8; it++) {
        int id = tid + 256 * it;
        int row = id >> 4, c = id & 15;
        float4 v = *(const float4*)&g_qkv[(size_t)(qt + row) * NQKV + h * HDD + c * 4];
        float* d = &Qs[row * 64 + ((c ^ (row & 7)) << 2)];
        d[0] = v.x * 0.125f; d[1] = v.y * 0.125f;
        d[2] = v.z * 0.125f; d[3] = v.w * 0.125f;
    }

    const int r0l = w * 16 + g;
    float m0 = -1e30f, m1 = -1e30f, l0 = 0.f, l1 = 0.f;
    float o_[8][4] = {};

    const int nkt = L >> 6;
    for (int kt = 0; kt < nkt; kt++) {
        __syncthreads();
        const size_t kr0 = (size_t)(base + kt * 64);
#pragma unroll
        for (int it = 0; it < 4; it++) {
            int id = tid + 256 * it;
            int row = id >> 4, c = id & 15;
            const float* src = &g_qkv[(kr0 + row) * NQKV + h * HDD + c * 4];
            unsigned off = (unsigned)(row * 64 + ((c ^ (row & 7)) << 2)) * 4;
            asm volatile("cp.async.ca.shared.global [%0],[%1],16;\n"
                         :: "r"(sK + off), "l"(&src[DIMM]));
            asm volatile("cp.async.ca.shared.global [%0],[%1],16;\n"
                         :: "r"(sV + off), "l"(&src[2 * DIMM]));
        }
        asm volatile("cp.async.commit_group;\n");
        asm volatile("cp.async.wait_group 0;\n");
        __syncthreads();

        float s[8][4] = {};
#pragma unroll
        for (int o = 0; o < 8; o++) {
            const int c0 = ((2 * o) ^ g) << 2, c1 = ((2 * o + 1) ^ g) << 2;
            unsigned a0 = __float_as_uint(Qs[ r0l      * 64 + c0 + t]);
            unsigned a2 = __float_as_uint(Qs[ r0l      * 64 + c1 + t]);
            unsigned a1 = __float_as_uint(Qs[(r0l + 8) * 64 + c0 + t]);
            unsigned a3 = __float_as_uint(Qs[(r0l + 8) * 64 + c1 + t]);
#pragma unroll
            for (int j = 0; j < 8; j++) {
                int rb = j * 8 + g;
                unsigned b0 = __float_as_uint(Ks[rb * 64 + c0 + t]);
                unsigned b1 = __float_as_uint(Ks[rb * 64 + c1 + t]);
                MMA_TF32(s[j], a0, a1, a2, a3, b0, b1);
            }
        }

        float rm0 = -1e30f, rm1 = -1e30f;
#pragma unroll
        for (int j = 0; j < 8; j++) {
            rm0 = fmaxf(rm0, fmaxf(s[j][0], s[j][1]));
            rm1 = fmaxf(rm1, fmaxf(s[j][2], s[j][3]));
        }
#pragma unroll
        for (int off = 1; off < 4; off <<= 1) {
            rm0 = fmaxf(rm0, __shfl_xor_sync(0xffffffffu, rm0, off));
            rm1 = fmaxf(rm1, __shfl_xor_sync(0xffffffffu, rm1, off));
        }
        float mn0 = fmaxf(m0, rm0), mn1 = fmaxf(m1, rm1);
        float f0 = __expf(m0 - mn0), f1 = __expf(m1 - mn1);
        float rs0 = 0.f, rs1 = 0.f;
#pragma unroll
        for (int j = 0; j < 8; j++) {
            s[j][0] = __expf(s[j][0] - mn0); rs0 += s[j][0];
            s[j][1] = __expf(s[j][1] - mn0); rs0 += s[j][1];
            s[j][2] = __expf(s[j][2] - mn1); rs1 += s[j][2];
            s[j][3] = __expf(s[j][3] - mn1); rs1 += s[j][3];
        }
#pragma unroll
        for (int off = 1; off < 4; off <<= 1) {
            rs0 += __shfl_xor_sync(0xffffffffu, rs0, off);
            rs1 += __shfl_xor_sync(0xffffffffu, rs1, off);
        }
        l0 = l0 * f0 + rs0;  m0 = mn0;
        l1 = l1 * f1 + rs1;  m1 = mn1;
#pragma unroll
        for (int j = 0; j < 8; j++) {
            o_[j][0] *= f0; o_[j][1] *= f0;
            o_[j][2] *= f1; o_[j][3] *= f1;
        }

#pragma unroll
        for (int j = 0; j < 8; j++) {
            int ch = 2 * j + (t >> 1);
            int wd = 2 * (t & 1);
            float* p0 = &Ps[ r0l      * 64 + ((ch ^ g) << 2) + wd];
            p0[0] = tf32rf(s[j][0]);
            p0[1] = tf32rf(s[j][1]);
            float* p1 = &Ps[(r0l + 8) * 64 + ((ch ^ g) << 2) + wd];
            p1[0] = tf32rf(s[j][2]);
            p1[1] = tf32rf(s[j][3]);
        }
        __syncwarp();

#pragma unroll
        for (int o = 0; o < 8; o++) {
            const int c0 = ((2 * o) ^ g) << 2, c1 = ((2 * o + 1) ^ g) << 2;
            unsigned a0 = __float_as_uint(Ps[ r0l      * 64 + c0 + t]);
            unsigned a2 = __float_as_uint(Ps[ r0l      * 64 + c1 + t]);
            unsigned a1 = __float_as_uint(Ps[(r0l + 8) * 64 + c0 + t]);
            unsigned a3 = __float_as_uint(Ps[(r0l + 8) * 64 + c1 + t]);
            const int kr  = 8 * o + t;
            const int kr2 = kr + 4;
#pragma unroll
            for (int j = 0; j < 8; j++) {
                int ch = 2 * j + (g >> 2);
                unsigned b0 = __float_as_uint(Vs[kr  * 64 + ((ch ^ (kr  & 7)) << 2) + (g & 3)]);
                unsigned b1 = __float_as_uint(Vs[kr2 * 64 + ((ch ^ (kr2 & 7)) << 2) + (g & 3)]);
                MMA_TF32(o_[j], a0, a1, a2, a3, b0, b1);
            }
        }
        __syncwarp();
    }

    const float npad = (float)(MAXLEN - L);
    float mf0 = (npad > 0.f) ? fmaxf(m0, 0.f) : m0;
    float mf1 = (npad > 0.f) ? fmaxf(m1, 0.f) : m1;
    float sc0 = __expf(m0 - mf0), sc1 = __expf(m1 - mf1);
    float w0 = sc0 / (l0 * sc0 + npad * __expf(-mf0));
    float w1 = sc1 / (l1 * sc1 + npad * __expf(-mf1));

    const int row0 = qt + r0l, row1 = row0 + 8;
#pragma unroll
    for (int j = 0; j < 8; j++) {
        int cn = h * HDD + j * 8 + 2 * t;
        *(float2*)&g_attn[(size_t)row0 * DIMM + cn] = make_float2(
            tf32rf(o_[j][0] * w0), tf32rf(o_[j][1] * w0));
        *(float2*)&g_attn[(size_t)row1 * DIMM + cn] = make_float2(
            tf32rf(o_[j][2] * w1), tf32rf(o_[j][3] * w1));
    }
}

// ---------------------------------------------------------------------------
extern "C" void kernel_launch(void* const* d_in, const int* in_sizes, int n_in,
                              void* d_out, int out_size)
{
    const float* hs   = (const float*)d_in[0];
    const float* wqkv = (const float*)d_in[1];
    const float* wo   = (const float*)d_in[2];
    const int*   cu   = (const int*)  d_in[3];
    float* out = (float*)d_out;

    float *qkv_p, *attn_p, *a_p, *w1_p, *w2_p;
    cudaGetSymbolAddress((void**)&qkv_p,  g_qkv);
    cudaGetSymbolAddress((void**)&attn_p, g_attn);
    cudaGetSymbolAddress((void**)&a_p,    g_a);
    cudaGetSymbolAddress((void**)&w1_p,   g_w1);
    cudaGetSymbolAddress((void**)&w2_p,   g_w2);

    const int v2_smem   = 2 * 49152;   // 96 KB
    const int mma_smem  = 65536;
    const int attn_smem = 98304;
    cudaFuncSetAttribute(gemm_v2,     cudaFuncAttributeMaxDynamicSharedMemorySize, v2_smem);
    cudaFuncSetAttribute(mma_gemm_nt, cudaFuncAttributeMaxDynamicSharedMemorySize, mma_smem);
    cudaFuncSetAttribute(attn_kernel, cudaFuncAttributeMaxDynamicSharedMemorySize, attn_smem);

    // 0) pre-round inputs/weights to tf32 (rna); reset flag
    zero_flag_kernel<<<1, 1>>>();
    cvt_tf32<<<(TOTAL * DIMM / 4 + 255) / 256, 256>>>(hs,   a_p,  TOTAL * DIMM / 4);
    cvt_tf32<<<(NQKV * DIMM / 4 + 255) / 256, 256>>>(wqkv, w1_p, NQKV * DIMM / 4);
    cvt_tf32<<<(DIMM * DIMM / 4 + 255) / 256, 256>>>(wo,   w2_p, DIMM * DIMM / 4);

    // 1) QKV projection: gemm_v2 -> spot check -> conditional proven fallback
    gemm_v2    <<<dim3(NQKV / 256, TOTAL / 128), 256, v2_smem >>>(
        a_p, w1_p, qkv_p, TOTAL, NQKV, DIMM, 1);
    check_gemm <<<16, 256>>>(a_p, w1_p, qkv_p, TOTAL, NQKV, DIMM);
    mma_gemm_nt<<<dim3(NQKV / 128, TOTAL / 128), 256, mma_smem>>>(
        a_p, w1_p, qkv_p, TOTAL, NQKV, DIMM, 1);

    // 2) RoPE (rounds q,k to tf32)
    rope_kernel<<<(TOTAL * 2 * NH * 32) / 256, 256>>>(cu);
    // 3) attention
    attn_kernel<<<dim3(TOTAL / 128, NH), 256, attn_smem>>>(cu);

    // 4) output projection (same flag governs fallback)
    gemm_v2    <<<dim3(DIMM / 256, TOTAL / 128), 256, v2_smem >>>(
        attn_p, w2_p, out, TOTAL, DIMM, DIMM, 0);
    mma_gemm_nt<<<dim3(DIMM / 128, TOTAL / 128), 256, mma_smem>>>(
        attn_p, w2_p, out, TOTAL, DIMM, DIMM, 0);
}

// round 10
// speedup vs baseline: 1.0336x; 1.0336x over previous
#include <cuda_runtime.h>
#include <math.h>
#include <stdint.h>

#define TOTAL   5120
#define DIMM    1024
#define NH      16
#define HDD     64
#define NB      4
#define MAXLEN  2048
#define NQKV    3072

// Scratch (device globals: no allocation allowed)
__device__ float g_qkv[(size_t)TOTAL * NQKV];    // q|k|v (tf32 values)
__device__ float g_attn[(size_t)TOTAL * DIMM];   // attention out (tf32 values)
__device__ float g_a [(size_t)TOTAL * DIMM];     // hs rounded to tf32
__device__ float g_w1[(size_t)NQKV * DIMM];      // Wqkv rounded to tf32
__device__ float g_w2[(size_t)DIMM * DIMM];      // Wo rounded to tf32
__device__ int   g_flag;                         // 1 => gemm_v3 bad, use fallback

extern __shared__ __align__(1024) uint8_t dynraw[];

__device__ __forceinline__ unsigned tf32r(float x) {
    unsigned u;
    asm("cvt.rna.tf32.f32 %0, %1;" : "=r"(u) : "f"(x));
    return u;
}
__device__ __forceinline__ float tf32rf(float x) {
    return __uint_as_float(tf32r(x));
}

#define MMA_TF32(acc, a0,a1,a2,a3, b0,b1)                                     \
    asm volatile("mma.sync.aligned.m16n8k8.row.col.f32.tf32.tf32.f32 "        \
                 "{%0,%1,%2,%3}, {%4,%5,%6,%7}, {%8,%9}, {%0,%1,%2,%3};"      \
                 : "+f"((acc)[0]), "+f"((acc)[1]), "+f"((acc)[2]), "+f"((acc)[3]) \
                 : "r"(a0), "r"(a1), "r"(a2), "r"(a3), "r"(b0), "r"(b1))

// ---------------------------------------------------------------------------
// Elementwise round-to-tf32 copy (vectorized).
// ---------------------------------------------------------------------------
__global__ void __launch_bounds__(256) cvt_tf32(const float* __restrict__ src,
                                                float* __restrict__ dst, int n4)
{
    int i = blockIdx.x * 256 + threadIdx.x;
    if (i >= n4) return;
    float4 v = ((const float4*)src)[i];
    v.x = tf32rf(v.x); v.y = tf32rf(v.y);
    v.z = tf32rf(v.z); v.w = tf32rf(v.w);
    ((float4*)dst)[i] = v;
}

// ---------------------------------------------------------------------------
// Flag + GEMM spot-check (4096 sampled dot products in fp32).
// ---------------------------------------------------------------------------
__global__ void zero_flag_kernel() { g_flag = 0; }

__global__ void __launch_bounds__(256) check_gemm(
    const float* __restrict__ A, const float* __restrict__ Bw,
    const float* __restrict__ C, int M, int N, int K)
{
    int s = blockIdx.x * 256 + threadIdx.x;
    int row = (int)(((unsigned)s * 2654435761u) % (unsigned)M);
    int col = (int)(((unsigned)s * 40503u + 17u) % (unsigned)N);
    const float* a = &A[(size_t)row * K];
    const float* b = &Bw[(size_t)col * K];
    float ref = 0.f;
    for (int k = 0; k < K; k += 4) {
        float4 av = *(const float4*)&a[k];
        float4 bv = *(const float4*)&b[k];
        ref += av.x * bv.x + av.y * bv.y + av.z * bv.z + av.w * bv.w;
    }
    float got = C[(size_t)row * N + col];
    if (fabsf(got - ref) > 1e-2f * (1.0f + fabsf(ref)))
        atomicOr(&g_flag, 1);
}

// ===========================================================================
// GEMM v3 (primary): proven 128x128 mma.sync tile, upgraded to a 3-stage
// cp.async ring with wait_group 1 (stage i+2 issued two compute blocks
// ahead). Buffers: 3 x (A 16KB + B 16KB) = 96KB, occ 2 (192KB/SM).
// Inputs pre-rounded tf32; no cvt in the inner loop.
// ===========================================================================
__global__ void __launch_bounds__(256, 2) gemm_v3(
    const float* __restrict__ A, const float* __restrict__ Bw,
    float* __restrict__ C, int M, int N, int K, int round_out)
{
    const int tid  = threadIdx.x;
    const int lane = tid & 31, w = tid >> 5;
    const int g = lane >> 2, t = lane & 3;
    const int wm = w >> 2, wn = w & 3;
    const int bm = blockIdx.y * 128, bn = blockIdx.x * 128;

    float acc[4][4][4] = {};

    const unsigned sbase = (unsigned)__cvta_generic_to_shared(dynraw);
    const int T = K >> 5;

#define V3_STAGE(j)                                                           \
    {                                                                         \
        if ((j) < T) {                                                        \
            unsigned base = sbase + (unsigned)((j) % 3) * 32768u;             \
            int k0 = (j) << 5;                                                \
            _Pragma("unroll")                                                 \
            for (int it = 0; it < 4; it++) {                                  \
                int id = tid + 256 * it;                                      \
                int row = id >> 3, c = id & 7;                                \
                unsigned off = (unsigned)(row * 32 + ((c ^ (row & 7)) << 2)) * 4; \
                asm volatile("cp.async.ca.shared.global [%0],[%1],16;\n"      \
                             :: "r"(base + off), "l"(&A [(size_t)(bm + row) * K + k0 + c * 4])); \
                asm volatile("cp.async.ca.shared.global [%0],[%1],16;\n"      \
                             :: "r"(base + 16384u + off), "l"(&Bw[(size_t)(bn + row) * K + k0 + c * 4])); \
            }                                                                 \
        }                                                                     \
        asm volatile("cp.async.commit_group;\n");                             \
    }

    V3_STAGE(0);
    V3_STAGE(1);

    for (int i = 0; i < T; i++) {
        asm volatile("cp.async.wait_group 1;\n");   // group i complete
        __syncthreads();                            // all warps past compute(i-1)
        V3_STAGE(i + 2);                            // overwrites buffer (i-1)%3

        const float* Ab = (const float*)(dynraw + (i % 3) * 32768);
        const float* Bb = (const float*)(dynraw + (i % 3) * 32768 + 16384);
#pragma unroll
        for (int o = 0; o < 4; o++) {
            const int c0 = ((2 * o) ^ g) << 2, c1 = ((2 * o + 1) ^ g) << 2;
            unsigned a[4][4], b[4][2];
#pragma unroll
            for (int mt = 0; mt < 4; mt++) {
                int r0 = wm * 64 + mt * 16 + g;
                a[mt][0] = __float_as_uint(Ab[ r0      * 32 + c0 + t]);
                a[mt][2] = __float_as_uint(Ab[ r0      * 32 + c1 + t]);
                a[mt][1] = __float_as_uint(Ab[(r0 + 8) * 32 + c0 + t]);
                a[mt][3] = __float_as_uint(Ab[(r0 + 8) * 32 + c1 + t]);
            }
#pragma unroll
            for (int nt = 0; nt < 4; nt++) {
                int r0 = wn * 32 + nt * 8 + g;
                b[nt][0] = __float_as_uint(Bb[r0 * 32 + c0 + t]);
                b[nt][1] = __float_as_uint(Bb[r0 * 32 + c1 + t]);
            }
#pragma unroll
            for (int mt = 0; mt < 4; mt++)
#pragma unroll
                for (int nt = 0; nt < 4; nt++)
                    MMA_TF32(acc[mt][nt], a[mt][0], a[mt][1], a[mt][2], a[mt][3],
                             b[nt][0], b[nt][1]);
        }
    }

#pragma unroll
    for (int mt = 0; mt < 4; mt++) {
        int r = bm + wm * 64 + mt * 16 + g;
#pragma unroll
        for (int nt = 0; nt < 4; nt++) {
            int cn = bn + wn * 32 + nt * 8 + 2 * t;
            float v0 = acc[mt][nt][0], v1 = acc[mt][nt][1];
            float v2 = acc[mt][nt][2], v3 = acc[mt][nt][3];
            if (round_out) {
                v0 = tf32rf(v0); v1 = tf32rf(v1); v2 = tf32rf(v2); v3 = tf32rf(v3);
            }
            *(float2*)&C[(size_t)r * N + cn]       = make_float2(v0, v1);
            *(float2*)&C[(size_t)(r + 8) * N + cn] = make_float2(v2, v3);
        }
    }
}

// ===========================================================================
// Fallback: R8-proven 2-stage 128x128 mma.sync GEMM — runs only if flagged.
// ===========================================================================
__global__ void __launch_bounds__(256, 2) mma_gemm_nt(
    const float* __restrict__ A, const float* __restrict__ Bw,
    float* __restrict__ C, int M, int N, int K, int round_out)
{
    if (g_flag == 0) return;                     // gemm_v3 verified good

    float* As = (float*)dynraw;                  // [2][128*32]
    float* Bs = (float*)dynraw + 8192;

    const int tid  = threadIdx.x;
    const int lane = tid & 31, w = tid >> 5;
    const int g = lane >> 2, t = lane & 3;
    const int wm = w >> 2, wn = w & 3;
    const int bm = blockIdx.y * 128, bn = blockIdx.x * 128;

    float acc[4][4][4] = {};

    const unsigned sA0 = (unsigned)__cvta_generic_to_shared(As);
    const unsigned sB0 = (unsigned)__cvta_generic_to_shared(Bs);

#define GEMM_STAGE(buf, k0)                                                   \
    {                                                                         \
        unsigned sa = sA0 + (buf) * 16384, sb = sB0 + (buf) * 16384;          \
        _Pragma("unroll")                                                     \
        for (int it = 0; it < 4; it++) {                                      \
            int id = tid + 256 * it;                                          \
            int row = id >> 3, c = id & 7;                                    \
            unsigned off = (unsigned)(row * 32 + ((c ^ (row & 7)) << 2)) * 4; \
            asm volatile("cp.async.ca.shared.global [%0],[%1],16;\n"          \
                         :: "r"(sa + off), "l"(&A [(size_t)(bm + row) * K + (k0) + c * 4])); \
            asm volatile("cp.async.ca.shared.global [%0],[%1],16;\n"          \
                         :: "r"(sb + off), "l"(&Bw[(size_t)(bn + row) * K + (k0) + c * 4])); \
        }                                                                     \
        asm volatile("cp.async.commit_group;\n");                             \
    }

    GEMM_STAGE(0, 0);
    int buf = 0;
    for (int k0 = 0; k0 < K; k0 += 32) {
        asm volatile("cp.async.wait_group 0;\n");
        __syncthreads();
        if (k0 + 32 < K) GEMM_STAGE(buf ^ 1, k0 + 32);

        const float* Ab = As + buf * 4096;
        const float* Bb = Bs + buf * 4096;
#pragma unroll
        for (int o = 0; o < 4; o++) {
            const int c0 = ((2 * o) ^ g) << 2, c1 = ((2 * o + 1) ^ g) << 2;
            unsigned a[4][4], b[4][2];
#pragma unroll
            for (int mt = 0; mt < 4; mt++) {
                int r0 = wm * 64 + mt * 16 + g;
                a[mt][0] = __float_as_uint(Ab[ r0      * 32 + c0 + t]);
                a[mt][2] = __float_as_uint(Ab[ r0      * 32 + c1 + t]);
                a[mt][1] = __float_as_uint(Ab[(r0 + 8) * 32 + c0 + t]);
                a[mt][3] = __float_as_uint(Ab[(r0 + 8) * 32 + c1 + t]);
            }
#pragma unroll
            for (int nt = 0; nt < 4; nt++) {
                int r0 = wn * 32 + nt * 8 + g;
                b[nt][0] = __float_as_uint(Bb[r0 * 32 + c0 + t]);
                b[nt][1] = __float_as_uint(Bb[r0 * 32 + c1 + t]);
            }
#pragma unroll
            for (int mt = 0; mt < 4; mt++)
#pragma unroll
                for (int nt = 0; nt < 4; nt++)
                    MMA_TF32(acc[mt][nt], a[mt][0], a[mt][1], a[mt][2], a[mt][3],
                             b[nt][0], b[nt][1]);
        }
        buf ^= 1;
    }

#pragma unroll
    for (int mt = 0; mt < 4; mt++) {
        int r = bm + wm * 64 + mt * 16 + g;
#pragma unroll
        for (int nt = 0; nt < 4; nt++) {
            int cn = bn + wn * 32 + nt * 8 + 2 * t;
            float v0 = acc[mt][nt][0], v1 = acc[mt][nt][1];
            float v2 = acc[mt][nt][2], v3 = acc[mt][nt][3];
            if (round_out) {
                v0 = tf32rf(v0); v1 = tf32rf(v1); v2 = tf32rf(v2); v3 = tf32rf(v3);
            }
            *(float2*)&C[(size_t)r * N + cn]       = make_float2(v0, v1);
            *(float2*)&C[(size_t)(r + 8) * N + cn] = make_float2(v2, v3);
        }
    }
}

// ---------------------------------------------------------------------------
// RoPE in-place on q,k sections of g_qkv; outputs rounded to tf32.
// ---------------------------------------------------------------------------
__global__ void __launch_bounds__(256) rope_kernel(const int* __restrict__ cu)
{
    int tt = blockIdx.x * 256 + threadIdx.x;
    int j  = tt & 31;
    int hh = (tt >> 5) & 15;
    int s  = (tt >> 9) & 1;
    int r  = tt >> 10;
    if (r >= TOTAL) return;

    int b = 0;
#pragma unroll
    for (int i = 1; i < NB; i++) if (r >= cu[i]) b = i;
    int pos = r - cu[b];

    float inv = exp2f(-(float)j * (13.287712379549449f / 32.0f));
    float fr  = (float)pos * inv;
    float c, sn;
    sincosf(fr, &sn, &c);

    float* base = g_qkv + (size_t)r * NQKV + s * DIMM + hh * HDD;
    float x1 = base[j], x2 = base[j + 32];
    base[j]      = tf32rf(x1 * c - x2 * sn);
    base[j + 32] = tf32rf(x2 * c + x1 * sn);
}

// ---------------------------------------------------------------------------
// Tensor-core flash attention (tf32, mma.sync). g_qkv holds tf32 values so
// staging is pure copies (Q x 0.125 exact). K/V staged via cp.async.
// ---------------------------------------------------------------------------
__global__ void __launch_bounds__(256, 2) attn_kernel(const int* __restrict__ cu)
{
    float* Qs = (float*)dynraw;             // 128*64
    float* Ks = (float*)dynraw + 8192;      // 64*64
    float* Vs = (float*)dynraw + 12288;     // 64*64
    float* Ps = (float*)dynraw + 16384;     // 128*64

    const int tid  = threadIdx.x;
    const int lane = tid & 31, w = tid >> 5;
    const int g = lane >> 2, t = lane & 3;
    const int h  = blockIdx.y;
    const int qt = blockIdx.x * 128;

    const unsigned sK = (unsigned)__cvta_generic_to_shared(Ks);
    const unsigned sV = (unsigned)__cvta_generic_to_shared(Vs);

    int b = 0;
#pragma unroll
    for (int i = 1; i < NB; i++) if (qt >= cu[i]) b = i;
    const int base = cu[b];
    const int L    = cu[b + 1] - base;

#pragma unroll
    for (int it = 0; it < 8; it++) {
        int id = tid + 256 * it;
        int row = id >> 4, c = id & 15;
        float4 v = *(const float4*)&g_qkv[(size_t)(qt + row) * NQKV + h * HDD + c * 4];
        float* d = &Qs[row * 64 + ((c ^ (row & 7)) << 2)];
        d[0] = v.x * 0.125f; d[1] = v.y * 0.125f;
        d[2] = v.z * 0.125f; d[3] = v.w * 0.125f;
    }

    const int r0l = w * 16 + g;
    float m0 = -1e30f, m1 = -1e30f, l0 = 0.f, l1 = 0.f;
    float o_[8][4] = {};

    const int nkt = L >> 6;
    for (int kt = 0; kt < nkt; kt++) {
        __syncthreads();
        const size_t kr0 = (size_t)(base + kt * 64);
#pragma unroll
        for (int it = 0; it < 4; it++) {
            int id = tid + 256 * it;
            int row = id >> 4, c = id & 15;
            const float* src = &g_qkv[(kr0 + row) * NQKV + h * HDD + c * 4];
            unsigned off = (unsigned)(row * 64 + ((c ^ (row & 7)) << 2)) * 4;
            asm volatile("cp.async.ca.shared.global [%0],[%1],16;\n"
                         :: "r"(sK + off), "l"(&src[DIMM]));
            asm volatile("cp.async.ca.shared.global [%0],[%1],16;\n"
                         :: "r"(sV + off), "l"(&src[2 * DIMM]));
        }
        asm volatile("cp.async.commit_group;\n");
        asm volatile("cp.async.wait_group 0;\n");
        __syncthreads();

        float s[8][4] = {};
#pragma unroll
        for (int o = 0; o < 8; o++) {
            const int c0 = ((2 * o) ^ g) << 2, c1 = ((2 * o + 1) ^ g) << 2;
            unsigned a0 = __float_as_uint(Qs[ r0l      * 64 + c0 + t]);
            unsigned a2 = __float_as_uint(Qs[ r0l      * 64 + c1 + t]);
            unsigned a1 = __float_as_uint(Qs[(r0l + 8) * 64 + c0 + t]);
            unsigned a3 = __float_as_uint(Qs[(r0l + 8) * 64 + c1 + t]);
#pragma unroll
            for (int j = 0; j < 8; j++) {
                int rb = j * 8 + g;
                unsigned b0 = __float_as_uint(Ks[rb * 64 + c0 + t]);
                unsigned b1 = __float_as_uint(Ks[rb * 64 + c1 + t]);
                MMA_TF32(s[j], a0, a1, a2, a3, b0, b1);
            }
        }

        float rm0 = -1e30f, rm1 = -1e30f;
#pragma unroll
        for (int j = 0; j < 8; j++) {
            rm0 = fmaxf(rm0, fmaxf(s[j][0], s[j][1]));
            rm1 = fmaxf(rm1, fmaxf(s[j][2], s[j][3]));
        }
#pragma unroll
        for (int off = 1; off < 4; off <<= 1) {
            rm0 = fmaxf(rm0, __shfl_xor_sync(0xffffffffu, rm0, off));
            rm1 = fmaxf(rm1, __shfl_xor_sync(0xffffffffu, rm1, off));
        }
        float mn0 = fmaxf(m0, rm0), mn1 = fmaxf(m1, rm1);
        float f0 = __expf(m0 - mn0), f1 = __expf(m1 - mn1);
        float rs0 = 0.f, rs1 = 0.f;
#pragma unroll
        for (int j = 0; j < 8; j++) {
            s[j][0] = __expf(s[j][0] - mn0); rs0 += s[j][0];
            s[j][1] = __expf(s[j][1] - mn0); rs0 += s[j][1];
            s[j][2] = __expf(s[j][2] - mn1); rs1 += s[j][2];
            s[j][3] = __expf(s[j][3] - mn1); rs1 += s[j][3];
        }
#pragma unroll
        for (int off = 1; off < 4; off <<= 1) {
            rs0 += __shfl_xor_sync(0xffffffffu, rs0, off);
            rs1 += __shfl_xor_sync(0xffffffffu, rs1, off);
        }
        l0 = l0 * f0 + rs0;  m0 = mn0;
        l1 = l1 * f1 + rs1;  m1 = mn1;
#pragma unroll
        for (int j = 0; j < 8; j++) {
            o_[j][0] *= f0; o_[j][1] *= f0;
            o_[j][2] *= f1; o_[j][3] *= f1;
        }

#pragma unroll
        for (int j = 0; j < 8; j++) {
            int ch = 2 * j + (t >> 1);
            int wd = 2 * (t & 1);
            float* p0 = &Ps[ r0l      * 64 + ((ch ^ g) << 2) + wd];
            p0[0] = tf32rf(s[j][0]);
            p0[1] = tf32rf(s[j][1]);
            float* p1 = &Ps[(r0l + 8) * 64 + ((ch ^ g) << 2) + wd];
            p1[0] = tf32rf(s[j][2]);
            p1[1] = tf32rf(s[j][3]);
        }
        __syncwarp();

#pragma unroll
        for (int o = 0; o < 8; o++) {
            const int c0 = ((2 * o) ^ g) << 2, c1 = ((2 * o + 1) ^ g) << 2;
            unsigned a0 = __float_as_uint(Ps[ r0l      * 64 + c0 + t]);
            unsigned a2 = __float_as_uint(Ps[ r0l      * 64 + c1 + t]);
            unsigned a1 = __float_as_uint(Ps[(r0l + 8) * 64 + c0 + t]);
            unsigned a3 = __float_as_uint(Ps[(r0l + 8) * 64 + c1 + t]);
            const int kr  = 8 * o + t;
            const int kr2 = kr + 4;
#pragma unroll
            for (int j = 0; j < 8; j++) {
                int ch = 2 * j + (g >> 2);
                unsigned b0 = __float_as_uint(Vs[kr  * 64 + ((ch ^ (kr  & 7)) << 2) + (g & 3)]);
                unsigned b1 = __float_as_uint(Vs[kr2 * 64 + ((ch ^ (kr2 & 7)) << 2) + (g & 3)]);
                MMA_TF32(o_[j], a0, a1, a2, a3, b0, b1);
            }
        }
        __syncwarp();
    }

    const float npad = (float)(MAXLEN - L);
    float mf0 = (npad > 0.f) ? fmaxf(m0, 0.f) : m0;
    float mf1 = (npad > 0.f) ? fmaxf(m1, 0.f) : m1;
    float sc0 = __expf(m0 - mf0), sc1 = __expf(m1 - mf1);
    float w0 = sc0 / (l0 * sc0 + npad * __expf(-mf0));
    float w1 = sc1 / (l1 * sc1 + npad * __expf(-mf1));

    const int row0 = qt + r0l, row1 = row0 + 8;
#pragma unroll
    for (int j = 0; j < 8; j++) {
        int cn = h * HDD + j * 8 + 2 * t;
        *(float2*)&g_attn[(size_t)row0 * DIMM + cn] = make_float2(
            tf32rf(o_[j][0] * w0), tf32rf(o_[j][1] * w0));
        *(float2*)&g_attn[(size_t)row1 * DIMM + cn] = make_float2(
            tf32rf(o_[j][2] * w1), tf32rf(o_[j][3] * w1));
    }
}

// ---------------------------------------------------------------------------
extern "C" void kernel_launch(void* const* d_in, const int* in_sizes, int n_in,
                              void* d_out, int out_size)
{
    const float* hs   = (const float*)d_in[0];
    const float* wqkv = (const float*)d_in[1];
    const float* wo   = (const float*)d_in[2];
    const int*   cu   = (const int*)  d_in[3];
    float* out = (float*)d_out;

    float *qkv_p, *attn_p, *a_p, *w1_p, *w2_p;
    cudaGetSymbolAddress((void**)&qkv_p,  g_qkv);
    cudaGetSymbolAddress((void**)&attn_p, g_attn);
    cudaGetSymbolAddress((void**)&a_p,    g_a);
    cudaGetSymbolAddress((void**)&w1_p,   g_w1);
    cudaGetSymbolAddress((void**)&w2_p,   g_w2);

    const int v3_smem   = 3 * 32768;   // 96 KB
    const int mma_smem  = 65536;
    const int attn_smem = 98304;
    cudaFuncSetAttribute(gemm_v3,     cudaFuncAttributeMaxDynamicSharedMemorySize, v3_smem);
    cudaFuncSetAttribute(mma_gemm_nt, cudaFuncAttributeMaxDynamicSharedMemorySize, mma_smem);
    cudaFuncSetAttribute(attn_kernel, cudaFuncAttributeMaxDynamicSharedMemorySize, attn_smem);

    // 0) pre-round inputs/weights to tf32 (rna); reset flag
    zero_flag_kernel<<<1, 1>>>();
    cvt_tf32<<<(TOTAL * DIMM / 4 + 255) / 256, 256>>>(hs,   a_p,  TOTAL * DIMM / 4);
    cvt_tf32<<<(NQKV * DIMM / 4 + 255) / 256, 256>>>(wqkv, w1_p, NQKV * DIMM / 4);
    cvt_tf32<<<(DIMM * DIMM / 4 + 255) / 256, 256>>>(wo,   w2_p, DIMM * DIMM / 4);

    // 1) QKV projection: gemm_v3 -> spot check -> conditional proven fallback
    gemm_v3    <<<dim3(NQKV / 128, TOTAL / 128), 256, v3_smem >>>(
        a_p, w1_p, qkv_p, TOTAL, NQKV, DIMM, 1);
    check_gemm <<<16, 256>>>(a_p, w1_p, qkv_p, TOTAL, NQKV, DIMM);
    mma_gemm_nt<<<dim3(NQKV / 128, TOTAL / 128), 256, mma_smem>>>(
        a_p, w1_p, qkv_p, TOTAL, NQKV, DIMM, 1);

    // 2) RoPE (rounds q,k to tf32)
    rope_kernel<<<(TOTAL * 2 * NH * 32) / 256, 256>>>(cu);
    // 3) attention
    attn_kernel<<<dim3(TOTAL / 128, NH), 256, attn_smem>>>(cu);

    // 4) output projection (same flag governs fallback)
    gemm_v3    <<<dim3(DIMM / 128, TOTAL / 128), 256, v3_smem >>>(
        attn_p, w2_p, out, TOTAL, DIMM, DIMM, 0);
    mma_gemm_nt<<<dim3(DIMM / 128, TOTAL / 128), 256, mma_smem>>>(
        attn_p, w2_p, out, TOTAL, DIMM, DIMM, 0);
}

// round 11
// speedup vs baseline: 1.1895x; 1.1508x over previous
#include <cuda_runtime.h>
#include <math.h>
#include <stdint.h>

#define TOTAL   5120
#define DIMM    1024
#define NH      16
#define HDD     64
#define NB      4
#define MAXLEN  2048
#define NQKV    3072

// Scratch (device globals: no allocation allowed)
__device__ float g_qkv[(size_t)TOTAL * NQKV];    // q|k|v (tf32 values)
__device__ float g_attn[(size_t)TOTAL * DIMM];   // attention out (tf32 values)
__device__ float g_a [(size_t)TOTAL * DIMM];     // hs rounded to tf32
__device__ float g_w1[(size_t)NQKV * DIMM];      // Wqkv rounded to tf32
__device__ float g_w2[(size_t)DIMM * DIMM];      // Wo rounded to tf32

extern __shared__ __align__(1024) uint8_t dynraw[];

__device__ __forceinline__ unsigned tf32r(float x) {
    unsigned u;
    asm("cvt.rna.tf32.f32 %0, %1;" : "=r"(u) : "f"(x));
    return u;
}
__device__ __forceinline__ float tf32rf(float x) {
    return __uint_as_float(tf32r(x));
}

#define MMA_TF32(acc, a0,a1,a2,a3, b0,b1)                                     \
    asm volatile("mma.sync.aligned.m16n8k8.row.col.f32.tf32.tf32.f32 "        \
                 "{%0,%1,%2,%3}, {%4,%5,%6,%7}, {%8,%9}, {%0,%1,%2,%3};"      \
                 : "+f"((acc)[0]), "+f"((acc)[1]), "+f"((acc)[2]), "+f"((acc)[3]) \
                 : "r"(a0), "r"(a1), "r"(a2), "r"(a3), "r"(b0), "r"(b1))

// ---------------------------------------------------------------------------
// Elementwise round-to-tf32 copy (vectorized).
// ---------------------------------------------------------------------------
__global__ void __launch_bounds__(256) cvt_tf32(const float* __restrict__ src,
                                                float* __restrict__ dst, int n4)
{
    int i = blockIdx.x * 256 + threadIdx.x;
    if (i >= n4) return;
    float4 v = ((const float4*)src)[i];
    v.x = tf32rf(v.x); v.y = tf32rf(v.y);
    v.z = tf32rf(v.z); v.w = tf32rf(v.w);
    ((float4*)dst)[i] = v;
}

// ===========================================================================
// Proven 2-stage 128x128 mma.sync tf32 GEMM NT (occ 2, 64KB smem).
// cp.async double-buffered, chunk-XOR swizzle (conflict-free LDS),
// inputs pre-rounded tf32 (no cvt in inner loop).
// ===========================================================================
__global__ void __launch_bounds__(256, 2) mma_gemm_nt(
    const float* __restrict__ A, const float* __restrict__ Bw,
    float* __restrict__ C, int M, int N, int K, int round_out)
{
    float* As = (float*)dynraw;                  // [2][128*32]
    float* Bs = (float*)dynraw + 8192;

    const int tid  = threadIdx.x;
    const int lane = tid & 31, w = tid >> 5;
    const int g = lane >> 2, t = lane & 3;
    const int wm = w >> 2, wn = w & 3;
    const int bm = blockIdx.y * 128, bn = blockIdx.x * 128;

    float acc[4][4][4] = {};

    const unsigned sA0 = (unsigned)__cvta_generic_to_shared(As);
    const unsigned sB0 = (unsigned)__cvta_generic_to_shared(Bs);

#define GEMM_STAGE(buf, k0)                                                   \
    {                                                                         \
        unsigned sa = sA0 + (buf) * 16384, sb = sB0 + (buf) * 16384;          \
        _Pragma("unroll")                                                     \
        for (int it = 0; it < 4; it++) {                                      \
            int id = tid + 256 * it;                                          \
            int row = id >> 3, c = id & 7;                                    \
            unsigned off = (unsigned)(row * 32 + ((c ^ (row & 7)) << 2)) * 4; \
            asm volatile("cp.async.ca.shared.global [%0],[%1],16;\n"          \
                         :: "r"(sa + off), "l"(&A [(size_t)(bm + row) * K + (k0) + c * 4])); \
            asm volatile("cp.async.ca.shared.global [%0],[%1],16;\n"          \
                         :: "r"(sb + off), "l"(&Bw[(size_t)(bn + row) * K + (k0) + c * 4])); \
        }                                                                     \
        asm volatile("cp.async.commit_group;\n");                             \
    }

    GEMM_STAGE(0, 0);
    int buf = 0;
    for (int k0 = 0; k0 < K; k0 += 32) {
        asm volatile("cp.async.wait_group 0;\n");
        __syncthreads();
        if (k0 + 32 < K) GEMM_STAGE(buf ^ 1, k0 + 32);

        const float* Ab = As + buf * 4096;
        const float* Bb = Bs + buf * 4096;
#pragma unroll
        for (int o = 0; o < 4; o++) {
            const int c0 = ((2 * o) ^ g) << 2, c1 = ((2 * o + 1) ^ g) << 2;
            unsigned a[4][4], b[4][2];
#pragma unroll
            for (int mt = 0; mt < 4; mt++) {
                int r0 = wm * 64 + mt * 16 + g;
                a[mt][0] = __float_as_uint(Ab[ r0      * 32 + c0 + t]);
                a[mt][2] = __float_as_uint(Ab[ r0      * 32 + c1 + t]);
                a[mt][1] = __float_as_uint(Ab[(r0 + 8) * 32 + c0 + t]);
                a[mt][3] = __float_as_uint(Ab[(r0 + 8) * 32 + c1 + t]);
            }
#pragma unroll
            for (int nt = 0; nt < 4; nt++) {
                int r0 = wn * 32 + nt * 8 + g;
                b[nt][0] = __float_as_uint(Bb[r0 * 32 + c0 + t]);
                b[nt][1] = __float_as_uint(Bb[r0 * 32 + c1 + t]);
            }
#pragma unroll
            for (int mt = 0; mt < 4; mt++)
#pragma unroll
                for (int nt = 0; nt < 4; nt++)
                    MMA_TF32(acc[mt][nt], a[mt][0], a[mt][1], a[mt][2], a[mt][3],
                             b[nt][0], b[nt][1]);
        }
        buf ^= 1;
    }

#pragma unroll
    for (int mt = 0; mt < 4; mt++) {
        int r = bm + wm * 64 + mt * 16 + g;
#pragma unroll
        for (int nt = 0; nt < 4; nt++) {
            int cn = bn + wn * 32 + nt * 8 + 2 * t;
            float v0 = acc[mt][nt][0], v1 = acc[mt][nt][1];
            float v2 = acc[mt][nt][2], v3 = acc[mt][nt][3];
            if (round_out) {
                v0 = tf32rf(v0); v1 = tf32rf(v1); v2 = tf32rf(v2); v3 = tf32rf(v3);
            }
            *(float2*)&C[(size_t)r * N + cn]       = make_float2(v0, v1);
            *(float2*)&C[(size_t)(r + 8) * N + cn] = make_float2(v2, v3);
        }
    }
}

// ---------------------------------------------------------------------------
// RoPE in-place on q,k sections of g_qkv; outputs rounded to tf32.
// ---------------------------------------------------------------------------
__global__ void __launch_bounds__(256) rope_kernel(const int* __restrict__ cu)
{
    int tt = blockIdx.x * 256 + threadIdx.x;
    int j  = tt & 31;
    int hh = (tt >> 5) & 15;
    int s  = (tt >> 9) & 1;
    int r  = tt >> 10;
    if (r >= TOTAL) return;

    int b = 0;
#pragma unroll
    for (int i = 1; i < NB; i++) if (r >= cu[i]) b = i;
    int pos = r - cu[b];

    float inv = exp2f(-(float)j * (13.287712379549449f / 32.0f));
    float fr  = (float)pos * inv;
    float c, sn;
    sincosf(fr, &sn, &c);

    float* base = g_qkv + (size_t)r * NQKV + s * DIMM + hh * HDD;
    float x1 = base[j], x2 = base[j + 32];
    base[j]      = tf32rf(x1 * c - x2 * sn);
    base[j + 32] = tf32rf(x2 * c + x1 * sn);
}

// ---------------------------------------------------------------------------
// Tensor-core flash attention (tf32, mma.sync). g_qkv holds tf32 values so
// staging is pure copies (Q x 0.125 exact). K/V staged via cp.async.
// Padded keys folded analytically into softmax denominator.
// ---------------------------------------------------------------------------
__global__ void __launch_bounds__(256, 2) attn_kernel(const int* __restrict__ cu)
{
    float* Qs = (float*)dynraw;             // 128*64
    float* Ks = (float*)dynraw + 8192;      // 64*64
    float* Vs = (float*)dynraw + 12288;     // 64*64
    float* Ps = (float*)dynraw + 16384;     // 128*64

    const int tid  = threadIdx.x;
    const int lane = tid & 31, w = tid >> 5;
    const int g = lane >> 2, t = lane & 3;
    const int h  = blockIdx.y;
    const int qt = blockIdx.x * 128;

    const unsigned sK = (unsigned)__cvta_generic_to_shared(Ks);
    const unsigned sV = (unsigned)__cvta_generic_to_shared(Vs);

    int b = 0;
#pragma unroll
    for (int i = 1; i < NB; i++) if (qt >= cu[i]) b = i;
    const int base = cu[b];
    const int L    = cu[b + 1] - base;

#pragma unroll
    for (int it = 0; it < 8; it++) {
        int id = tid + 256 * it;
        int row = id >> 4, c = id & 15;
        float4 v = *(const float4*)&g_qkv[(size_t)(qt + row) * NQKV + h * HDD + c * 4];
        float* d = &Qs[row * 64 + ((c ^ (row & 7)) << 2)];
        d[0] = v.x * 0.125f; d[1] = v.y * 0.125f;
        d[2] = v.z * 0.125f; d[3] = v.w * 0.125f;
    }

    const int r0l = w * 16 + g;
    float m0 = -1e30f, m1 = -1e30f, l0 = 0.f, l1 = 0.f;
    float o_[8][4] = {};

    const int nkt = L >> 6;
    for (int kt = 0; kt < nkt; kt++) {
        __syncthreads();
        const size_t kr0 = (size_t)(base + kt * 64);
#pragma unroll
        for (int it = 0; it < 4; it++) {
            int id = tid + 256 * it;
            int row = id >> 4, c = id & 15;
            const float* src = &g_qkv[(kr0 + row) * NQKV + h * HDD + c * 4];
            unsigned off = (unsigned)(row * 64 + ((c ^ (row & 7)) << 2)) * 4;
            asm volatile("cp.async.ca.shared.global [%0],[%1],16;\n"
                         :: "r"(sK + off), "l"(&src[DIMM]));
            asm volatile("cp.async.ca.shared.global [%0],[%1],16;\n"
                         :: "r"(sV + off), "l"(&src[2 * DIMM]));
        }
        asm volatile("cp.async.commit_group;\n");
        asm volatile("cp.async.wait_group 0;\n");
        __syncthreads();

        float s[8][4] = {};
#pragma unroll
        for (int o = 0; o < 8; o++) {
            const int c0 = ((2 * o) ^ g) << 2, c1 = ((2 * o + 1) ^ g) << 2;
            unsigned a0 = __float_as_uint(Qs[ r0l      * 64 + c0 + t]);
            unsigned a2 = __float_as_uint(Qs[ r0l      * 64 + c1 + t]);
            unsigned a1 = __float_as_uint(Qs[(r0l + 8) * 64 + c0 + t]);
            unsigned a3 = __float_as_uint(Qs[(r0l + 8) * 64 + c1 + t]);
#pragma unroll
            for (int j = 0; j < 8; j++) {
                int rb = j * 8 + g;
                unsigned b0 = __float_as_uint(Ks[rb * 64 + c0 + t]);
                unsigned b1 = __float_as_uint(Ks[rb * 64 + c1 + t]);
                MMA_TF32(s[j], a0, a1, a2, a3, b0, b1);
            }
        }

        float rm0 = -1e30f, rm1 = -1e30f;
#pragma unroll
        for (int j = 0; j < 8; j++) {
            rm0 = fmaxf(rm0, fmaxf(s[j][0], s[j][1]));
            rm1 = fmaxf(rm1, fmaxf(s[j][2], s[j][3]));
        }
#pragma unroll
        for (int off = 1; off < 4; off <<= 1) {
            rm0 = fmaxf(rm0, __shfl_xor_sync(0xffffffffu, rm0, off));
            rm1 = fmaxf(rm1, __shfl_xor_sync(0xffffffffu, rm1, off));
        }
        float mn0 = fmaxf(m0, rm0), mn1 = fmaxf(m1, rm1);
        float f0 = __expf(m0 - mn0), f1 = __expf(m1 - mn1);
        float rs0 = 0.f, rs1 = 0.f;
#pragma unroll
        for (int j = 0; j < 8; j++) {
            s[j][0] = __expf(s[j][0] - mn0); rs0 += s[j][0];
            s[j][1] = __expf(s[j][1] - mn0); rs0 += s[j][1];
            s[j][2] = __expf(s[j][2] - mn1); rs1 += s[j][2];
            s[j][3] = __expf(s[j][3] - mn1); rs1 += s[j][3];
        }
#pragma unroll
        for (int off = 1; off < 4; off <<= 1) {
            rs0 += __shfl_xor_sync(0xffffffffu, rs0, off);
            rs1 += __shfl_xor_sync(0xffffffffu, rs1, off);
        }
        l0 = l0 * f0 + rs0;  m0 = mn0;
        l1 = l1 * f1 + rs1;  m1 = mn1;
#pragma unroll
        for (int j = 0; j < 8; j++) {
            o_[j][0] *= f0; o_[j][1] *= f0;
            o_[j][2] *= f1; o_[j][3] *= f1;
        }

#pragma unroll
        for (int j = 0; j < 8; j++) {
            int ch = 2 * j + (t >> 1);
            int wd = 2 * (t & 1);
            float* p0 = &Ps[ r0l      * 64 + ((ch ^ g) << 2) + wd];
            p0[0] = tf32rf(s[j][0]);
            p0[1] = tf32rf(s[j][1]);
            float* p1 = &Ps[(r0l + 8) * 64 + ((ch ^ g) << 2) + wd];
            p1[0] = tf32rf(s[j][2]);
            p1[1] = tf32rf(s[j][3]);
        }
        __syncwarp();

#pragma unroll
        for (int o = 0; o < 8; o++) {
            const int c0 = ((2 * o) ^ g) << 2, c1 = ((2 * o + 1) ^ g) << 2;
            unsigned a0 = __float_as_uint(Ps[ r0l      * 64 + c0 + t]);
            unsigned a2 = __float_as_uint(Ps[ r0l      * 64 + c1 + t]);
            unsigned a1 = __float_as_uint(Ps[(r0l + 8) * 64 + c0 + t]);
            unsigned a3 = __float_as_uint(Ps[(r0l + 8) * 64 + c1 + t]);
            const int kr  = 8 * o + t;
            const int kr2 = kr + 4;
#pragma unroll
            for (int j = 0; j < 8; j++) {
                int ch = 2 * j + (g >> 2);
                unsigned b0 = __float_as_uint(Vs[kr  * 64 + ((ch ^ (kr  & 7)) << 2) + (g & 3)]);
                unsigned b1 = __float_as_uint(Vs[kr2 * 64 + ((ch ^ (kr2 & 7)) << 2) + (g & 3)]);
                MMA_TF32(o_[j], a0, a1, a2, a3, b0, b1);
            }
        }
        __syncwarp();
    }

    const float npad = (float)(MAXLEN - L);
    float mf0 = (npad > 0.f) ? fmaxf(m0, 0.f) : m0;
    float mf1 = (npad > 0.f) ? fmaxf(m1, 0.f) : m1;
    float sc0 = __expf(m0 - mf0), sc1 = __expf(m1 - mf1);
    float w0 = sc0 / (l0 * sc0 + npad * __expf(-mf0));
    float w1 = sc1 / (l1 * sc1 + npad * __expf(-mf1));

    const int row0 = qt + r0l, row1 = row0 + 8;
#pragma unroll
    for (int j = 0; j < 8; j++) {
        int cn = h * HDD + j * 8 + 2 * t;
        *(float2*)&g_attn[(size_t)row0 * DIMM + cn] = make_float2(
            tf32rf(o_[j][0] * w0), tf32rf(o_[j][1] * w0));
        *(float2*)&g_attn[(size_t)row1 * DIMM + cn] = make_float2(
            tf32rf(o_[j][2] * w1), tf32rf(o_[j][3] * w1));
    }
}

// ---------------------------------------------------------------------------
extern "C" void kernel_launch(void* const* d_in, const int* in_sizes, int n_in,
                              void* d_out, int out_size)
{
    const float* hs   = (const float*)d_in[0];
    const float* wqkv = (const float*)d_in[1];
    const float* wo   = (const float*)d_in[2];
    const int*   cu   = (const int*)  d_in[3];
    float* out = (float*)d_out;

    float *qkv_p, *attn_p, *a_p, *w1_p, *w2_p;
    cudaGetSymbolAddress((void**)&qkv_p,  g_qkv);
    cudaGetSymbolAddress((void**)&attn_p, g_attn);
    cudaGetSymbolAddress((void**)&a_p,    g_a);
    cudaGetSymbolAddress((void**)&w1_p,   g_w1);
    cudaGetSymbolAddress((void**)&w2_p,   g_w2);

    const int mma_smem  = 65536;
    const int attn_smem = 98304;
    cudaFuncSetAttribute(mma_gemm_nt, cudaFuncAttributeMaxDynamicSharedMemorySize, mma_smem);
    cudaFuncSetAttribute(attn_kernel, cudaFuncAttributeMaxDynamicSharedMemorySize, attn_smem);

    // 0) pre-round inputs/weights to tf32 (rna)
    cvt_tf32<<<(TOTAL * DIMM / 4 + 255) / 256, 256>>>(hs,   a_p,  TOTAL * DIMM / 4);
    cvt_tf32<<<(NQKV * DIMM / 4 + 255) / 256, 256>>>(wqkv, w1_p, NQKV * DIMM / 4);
    cvt_tf32<<<(DIMM * DIMM / 4 + 255) / 256, 256>>>(wo,   w2_p, DIMM * DIMM / 4);

    // 1) QKV projection
    mma_gemm_nt<<<dim3(NQKV / 128, TOTAL / 128), 256, mma_smem>>>(
        a_p, w1_p, qkv_p, TOTAL, NQKV, DIMM, 1);
    // 2) RoPE (rounds q,k to tf32)
    rope_kernel<<<(TOTAL * 2 * NH * 32) / 256, 256>>>(cu);
    // 3) attention
    attn_kernel<<<dim3(TOTAL / 128, NH), 256, attn_smem>>>(cu);
    // 4) output projection
    mma_gemm_nt<<<dim3(DIMM / 128, TOTAL / 128), 256, mma_smem>>>(
        attn_p, w2_p, out, TOTAL, DIMM, DIMM, 0);
}

// round 12
// speedup vs baseline: 1.2220x; 1.0273x over previous
#include <cuda_runtime.h>
#include <math.h>
#include <stdint.h>

#define TOTAL   5120
#define DIMM    1024
#define NH      16
#define HDD     64
#define NB      4
#define MAXLEN  2048
#define NQKV    3072

// Scratch (device globals: no allocation allowed)
__device__ float g_qkv[(size_t)TOTAL * NQKV];    // q|k|v (tf32 values)
__device__ float g_attn[(size_t)TOTAL * DIMM];   // attention out (tf32 values)
__device__ float g_a [(size_t)TOTAL * DIMM];     // hs rounded to tf32
__device__ float g_w1[(size_t)NQKV * DIMM];      // Wqkv rounded to tf32
__device__ float g_w2[(size_t)DIMM * DIMM];      // Wo rounded to tf32

extern __shared__ __align__(1024) uint8_t dynraw[];

__device__ __forceinline__ unsigned tf32r(float x) {
    unsigned u;
    asm("cvt.rna.tf32.f32 %0, %1;" : "=r"(u) : "f"(x));
    return u;
}
__device__ __forceinline__ float tf32rf(float x) {
    return __uint_as_float(tf32r(x));
}

#define MMA_TF32(acc, a0,a1,a2,a3, b0,b1)                                     \
    asm volatile("mma.sync.aligned.m16n8k8.row.col.f32.tf32.tf32.f32 "        \
                 "{%0,%1,%2,%3}, {%4,%5,%6,%7}, {%8,%9}, {%0,%1,%2,%3};"      \
                 : "+f"((acc)[0]), "+f"((acc)[1]), "+f"((acc)[2]), "+f"((acc)[3]) \
                 : "r"(a0), "r"(a1), "r"(a2), "r"(a3), "r"(b0), "r"(b1))

// ---------------------------------------------------------------------------
// Elementwise round-to-tf32 copy (vectorized).
// ---------------------------------------------------------------------------
__global__ void __launch_bounds__(256) cvt_tf32(const float* __restrict__ src,
                                                float* __restrict__ dst, int n4)
{
    int i = blockIdx.x * 256 + threadIdx.x;
    if (i >= n4) return;
    float4 v = ((const float4*)src)[i];
    v.x = tf32rf(v.x); v.y = tf32rf(v.y);
    v.z = tf32rf(v.z); v.w = tf32rf(v.w);
    ((float4*)dst)[i] = v;
}

// ===========================================================================
// Proven 2-stage 128x128 mma.sync tf32 GEMM NT (occ 2, 64KB smem).
// ===========================================================================
__global__ void __launch_bounds__(256, 2) mma_gemm_nt(
    const float* __restrict__ A, const float* __restrict__ Bw,
    float* __restrict__ C, int M, int N, int K, int round_out)
{
    float* As = (float*)dynraw;                  // [2][128*32]
    float* Bs = (float*)dynraw + 8192;

    const int tid  = threadIdx.x;
    const int lane = tid & 31, w = tid >> 5;
    const int g = lane >> 2, t = lane & 3;
    const int wm = w >> 2, wn = w & 3;
    const int bm = blockIdx.y * 128, bn = blockIdx.x * 128;

    float acc[4][4][4] = {};

    const unsigned sA0 = (unsigned)__cvta_generic_to_shared(As);
    const unsigned sB0 = (unsigned)__cvta_generic_to_shared(Bs);

#define GEMM_STAGE(buf, k0)                                                   \
    {                                                                         \
        unsigned sa = sA0 + (buf) * 16384, sb = sB0 + (buf) * 16384;          \
        _Pragma("unroll")                                                     \
        for (int it = 0; it < 4; it++) {                                      \
            int id = tid + 256 * it;                                          \
            int row = id >> 3, c = id & 7;                                    \
            unsigned off = (unsigned)(row * 32 + ((c ^ (row & 7)) << 2)) * 4; \
            asm volatile("cp.async.ca.shared.global [%0],[%1],16;\n"          \
                         :: "r"(sa + off), "l"(&A [(size_t)(bm + row) * K + (k0) + c * 4])); \
            asm volatile("cp.async.ca.shared.global [%0],[%1],16;\n"          \
                         :: "r"(sb + off), "l"(&Bw[(size_t)(bn + row) * K + (k0) + c * 4])); \
        }                                                                     \
        asm volatile("cp.async.commit_group;\n");                             \
    }

    GEMM_STAGE(0, 0);
    int buf = 0;
    for (int k0 = 0; k0 < K; k0 += 32) {
        asm volatile("cp.async.wait_group 0;\n");
        __syncthreads();
        if (k0 + 32 < K) GEMM_STAGE(buf ^ 1, k0 + 32);

        const float* Ab = As + buf * 4096;
        const float* Bb = Bs + buf * 4096;
#pragma unroll
        for (int o = 0; o < 4; o++) {
            const int c0 = ((2 * o) ^ g) << 2, c1 = ((2 * o + 1) ^ g) << 2;
            unsigned a[4][4], b[4][2];
#pragma unroll
            for (int mt = 0; mt < 4; mt++) {
                int r0 = wm * 64 + mt * 16 + g;
                a[mt][0] = __float_as_uint(Ab[ r0      * 32 + c0 + t]);
                a[mt][2] = __float_as_uint(Ab[ r0      * 32 + c1 + t]);
                a[mt][1] = __float_as_uint(Ab[(r0 + 8) * 32 + c0 + t]);
                a[mt][3] = __float_as_uint(Ab[(r0 + 8) * 32 + c1 + t]);
            }
#pragma unroll
            for (int nt = 0; nt < 4; nt++) {
                int r0 = wn * 32 + nt * 8 + g;
                b[nt][0] = __float_as_uint(Bb[r0 * 32 + c0 + t]);
                b[nt][1] = __float_as_uint(Bb[r0 * 32 + c1 + t]);
            }
#pragma unroll
            for (int mt = 0; mt < 4; mt++)
#pragma unroll
                for (int nt = 0; nt < 4; nt++)
                    MMA_TF32(acc[mt][nt], a[mt][0], a[mt][1], a[mt][2], a[mt][3],
                             b[nt][0], b[nt][1]);
        }
        buf ^= 1;
    }

#pragma unroll
    for (int mt = 0; mt < 4; mt++) {
        int r = bm + wm * 64 + mt * 16 + g;
#pragma unroll
        for (int nt = 0; nt < 4; nt++) {
            int cn = bn + wn * 32 + nt * 8 + 2 * t;
            float v0 = acc[mt][nt][0], v1 = acc[mt][nt][1];
            float v2 = acc[mt][nt][2], v3 = acc[mt][nt][3];
            if (round_out) {
                v0 = tf32rf(v0); v1 = tf32rf(v1); v2 = tf32rf(v2); v3 = tf32rf(v3);
            }
            *(float2*)&C[(size_t)r * N + cn]       = make_float2(v0, v1);
            *(float2*)&C[(size_t)(r + 8) * N + cn] = make_float2(v2, v3);
        }
    }
}

// ---------------------------------------------------------------------------
// RoPE in-place on q,k sections of g_qkv; outputs rounded to tf32.
// ---------------------------------------------------------------------------
__global__ void __launch_bounds__(256) rope_kernel(const int* __restrict__ cu)
{
    int tt = blockIdx.x * 256 + threadIdx.x;
    int j  = tt & 31;
    int hh = (tt >> 5) & 15;
    int s  = (tt >> 9) & 1;
    int r  = tt >> 10;
    if (r >= TOTAL) return;

    int b = 0;
#pragma unroll
    for (int i = 1; i < NB; i++) if (r >= cu[i]) b = i;
    int pos = r - cu[b];

    float inv = exp2f(-(float)j * (13.287712379549449f / 32.0f));
    float fr  = (float)pos * inv;
    float c, sn;
    sincosf(fr, &sn, &c);

    float* base = g_qkv + (size_t)r * NQKV + s * DIMM + hh * HDD;
    float x1 = base[j], x2 = base[j + 32];
    base[j]      = tf32rf(x1 * c - x2 * sn);
    base[j + 32] = tf32rf(x2 * c + x1 * sn);
}

// ---------------------------------------------------------------------------
// Tensor-core flash attention (tf32, mma.sync) with single-buffer cp.async
// PREFETCH pipeline: K(i+1) loads overlap PV(i); V(i+1) loads overlap
// QK^T(i+1)+softmax. Separate commit groups for K and V; unconditional
// commits keep group counts uniform. No extra smem; occ 2 preserved.
// Padded keys folded analytically into softmax denominator.
// ---------------------------------------------------------------------------
__global__ void __launch_bounds__(256, 2) attn_kernel(const int* __restrict__ cu)
{
    float* Qs = (float*)dynraw;             // 128*64
    float* Ks = (float*)dynraw + 8192;      // 64*64
    float* Vs = (float*)dynraw + 12288;     // 64*64
    float* Ps = (float*)dynraw + 16384;     // 128*64

    const int tid  = threadIdx.x;
    const int lane = tid & 31, w = tid >> 5;
    const int g = lane >> 2, t = lane & 3;
    const int h  = blockIdx.y;
    const int qt = blockIdx.x * 128;

    const unsigned sK = (unsigned)__cvta_generic_to_shared(Ks);
    const unsigned sV = (unsigned)__cvta_generic_to_shared(Vs);

    int b = 0;
#pragma unroll
    for (int i = 1; i < NB; i++) if (qt >= cu[i]) b = i;
    const int base = cu[b];
    const int L    = cu[b + 1] - base;
    const int nkt  = L >> 6;

    // K / V tile staging (each thread: 4 16B chunks). Unconditional commit.
#define STAGE_K(j)                                                            \
    {                                                                         \
        if ((j) < nkt) {                                                      \
            const size_t kr0 = (size_t)(base + (j) * 64);                     \
            _Pragma("unroll")                                                 \
            for (int it = 0; it < 4; it++) {                                  \
                int id = tid + 256 * it;                                      \
                int row = id >> 4, c = id & 15;                               \
                unsigned off = (unsigned)(row * 64 + ((c ^ (row & 7)) << 2)) * 4; \
                asm volatile("cp.async.ca.shared.global [%0],[%1],16;\n"      \
                    :: "r"(sK + off),                                         \
                       "l"(&g_qkv[(kr0 + row) * NQKV + h * HDD + c * 4 + DIMM])); \
            }                                                                 \
        }                                                                     \
        asm volatile("cp.async.commit_group;\n");                             \
    }
#define STAGE_V(j)                                                            \
    {                                                                         \
        if ((j) < nkt) {                                                      \
            const size_t kr0 = (size_t)(base + (j) * 64);                     \
            _Pragma("unroll")                                                 \
            for (int it = 0; it < 4; it++) {                                  \
                int id = tid + 256 * it;                                      \
                int row = id >> 4, c = id & 15;                               \
                unsigned off = (unsigned)(row * 64 + ((c ^ (row & 7)) << 2)) * 4; \
                asm volatile("cp.async.ca.shared.global [%0],[%1],16;\n"      \
                    :: "r"(sV + off),                                         \
                       "l"(&g_qkv[(kr0 + row) * NQKV + h * HDD + c * 4 + 2 * DIMM])); \
            }                                                                 \
        }                                                                     \
        asm volatile("cp.async.commit_group;\n");                             \
    }

    // Stage Q (plain stores; tf32 values, x0.125 exact) + prefetch K0, V0.
#pragma unroll
    for (int it = 0; it < 8; it++) {
        int id = tid + 256 * it;
        int row = id >> 4, c = id & 15;
        float4 v = *(const float4*)&g_qkv[(size_t)(qt + row) * NQKV + h * HDD + c * 4];
        float* d = &Qs[row * 64 + ((c ^ (row & 7)) << 2)];
        d[0] = v.x * 0.125f; d[1] = v.y * 0.125f;
        d[2] = v.z * 0.125f; d[3] = v.w * 0.125f;
    }
    STAGE_K(0);
    STAGE_V(0);

    const int r0l = w * 16 + g;
    float m0 = -1e30f, m1 = -1e30f, l0 = 0.f, l1 = 0.f;
    float o_[8][4] = {};

    for (int kt = 0; kt < nkt; kt++) {
        // pending groups: {K(kt), V(kt)} -> wait for K(kt), leave V in flight
        asm volatile("cp.async.wait_group 1;\n");
        __syncthreads();                         // K visible (also Qs on kt=0)

        // ---- S = Q K^T ----
        float s[8][4] = {};
#pragma unroll
        for (int o = 0; o < 8; o++) {
            const int c0 = ((2 * o) ^ g) << 2, c1 = ((2 * o + 1) ^ g) << 2;
            unsigned a0 = __float_as_uint(Qs[ r0l      * 64 + c0 + t]);
            unsigned a2 = __float_as_uint(Qs[ r0l      * 64 + c1 + t]);
            unsigned a1 = __float_as_uint(Qs[(r0l + 8) * 64 + c0 + t]);
            unsigned a3 = __float_as_uint(Qs[(r0l + 8) * 64 + c1 + t]);
#pragma unroll
            for (int j = 0; j < 8; j++) {
                int rb = j * 8 + g;
                unsigned b0 = __float_as_uint(Ks[rb * 64 + c0 + t]);
                unsigned b1 = __float_as_uint(Ks[rb * 64 + c1 + t]);
                MMA_TF32(s[j], a0, a1, a2, a3, b0, b1);
            }
        }

        // ---- online softmax ----
        float rm0 = -1e30f, rm1 = -1e30f;
#pragma unroll
        for (int j = 0; j < 8; j++) {
            rm0 = fmaxf(rm0, fmaxf(s[j][0], s[j][1]));
            rm1 = fmaxf(rm1, fmaxf(s[j][2], s[j][3]));
        }
#pragma unroll
        for (int off = 1; off < 4; off <<= 1) {
            rm0 = fmaxf(rm0, __shfl_xor_sync(0xffffffffu, rm0, off));
            rm1 = fmaxf(rm1, __shfl_xor_sync(0xffffffffu, rm1, off));
        }
        float mn0 = fmaxf(m0, rm0), mn1 = fmaxf(m1, rm1);
        float f0 = __expf(m0 - mn0), f1 = __expf(m1 - mn1);
        float rs0 = 0.f, rs1 = 0.f;
#pragma unroll
        for (int j = 0; j < 8; j++) {
            s[j][0] = __expf(s[j][0] - mn0); rs0 += s[j][0];
            s[j][1] = __expf(s[j][1] - mn0); rs0 += s[j][1];
            s[j][2] = __expf(s[j][2] - mn1); rs1 += s[j][2];
            s[j][3] = __expf(s[j][3] - mn1); rs1 += s[j][3];
        }
#pragma unroll
        for (int off = 1; off < 4; off <<= 1) {
            rs0 += __shfl_xor_sync(0xffffffffu, rs0, off);
            rs1 += __shfl_xor_sync(0xffffffffu, rs1, off);
        }
        l0 = l0 * f0 + rs0;  m0 = mn0;
        l1 = l1 * f1 + rs1;  m1 = mn1;
#pragma unroll
        for (int j = 0; j < 8; j++) {
            o_[j][0] *= f0; o_[j][1] *= f0;
            o_[j][2] *= f1; o_[j][3] *= f1;
        }

        // ---- P -> warp-local swizzled smem ----
#pragma unroll
        for (int j = 0; j < 8; j++) {
            int ch = 2 * j + (t >> 1);
            int wd = 2 * (t & 1);
            float* p0 = &Ps[ r0l      * 64 + ((ch ^ g) << 2) + wd];
            p0[0] = tf32rf(s[j][0]);
            p0[1] = tf32rf(s[j][1]);
            float* p1 = &Ps[(r0l + 8) * 64 + ((ch ^ g) << 2) + wd];
            p1[0] = tf32rf(s[j][2]);
            p1[1] = tf32rf(s[j][3]);
        }
        __syncwarp();

        // ---- V(kt) ready; barrier doubles as "all K reads done" ----
        asm volatile("cp.async.wait_group 0;\n");
        __syncthreads();

        // ---- prefetch K(kt+1) into Ks (overlaps PV) ----
        STAGE_K(kt + 1);

        // ---- O += P V ----
#pragma unroll
        for (int o = 0; o < 8; o++) {
            const int c0 = ((2 * o) ^ g) << 2, c1 = ((2 * o + 1) ^ g) << 2;
            unsigned a0 = __float_as_uint(Ps[ r0l      * 64 + c0 + t]);
            unsigned a2 = __float_as_uint(Ps[ r0l      * 64 + c1 + t]);
            unsigned a1 = __float_as_uint(Ps[(r0l + 8) * 64 + c0 + t]);
            unsigned a3 = __float_as_uint(Ps[(r0l + 8) * 64 + c1 + t]);
            const int kr  = 8 * o + t;
            const int kr2 = kr + 4;
#pragma unroll
            for (int j = 0; j < 8; j++) {
                int ch = 2 * j + (g >> 2);
                unsigned b0 = __float_as_uint(Vs[kr  * 64 + ((ch ^ (kr  & 7)) << 2) + (g & 3)]);
                unsigned b1 = __float_as_uint(Vs[kr2 * 64 + ((ch ^ (kr2 & 7)) << 2) + (g & 3)]);
                MMA_TF32(o_[j], a0, a1, a2, a3, b0, b1);
            }
        }
        __syncwarp();                            // P reads done (warp-local)

        __syncthreads();                         // all V reads done
        // ---- prefetch V(kt+1) into Vs (overlaps next QK^T+softmax) ----
        STAGE_V(kt + 1);
    }

    // epilogue: fold padded keys, normalize, store (tf32-rounded for GEMM2)
    const float npad = (float)(MAXLEN - L);
    float mf0 = (npad > 0.f) ? fmaxf(m0, 0.f) : m0;
    float mf1 = (npad > 0.f) ? fmaxf(m1, 0.f) : m1;
    float sc0 = __expf(m0 - mf0), sc1 = __expf(m1 - mf1);
    float w0 = sc0 / (l0 * sc0 + npad * __expf(-mf0));
    float w1 = sc1 / (l1 * sc1 + npad * __expf(-mf1));

    const int row0 = qt + r0l, row1 = row0 + 8;
#pragma unroll
    for (int j = 0; j < 8; j++) {
        int cn = h * HDD + j * 8 + 2 * t;
        *(float2*)&g_attn[(size_t)row0 * DIMM + cn] = make_float2(
            tf32rf(o_[j][0] * w0), tf32rf(o_[j][1] * w0));
        *(float2*)&g_attn[(size_t)row1 * DIMM + cn] = make_float2(
            tf32rf(o_[j][2] * w1), tf32rf(o_[j][3] * w1));
    }
}

// ---------------------------------------------------------------------------
extern "C" void kernel_launch(void* const* d_in, const int* in_sizes, int n_in,
                              void* d_out, int out_size)
{
    const float* hs   = (const float*)d_in[0];
    const float* wqkv = (const float*)d_in[1];
    const float* wo   = (const float*)d_in[2];
    const int*   cu   = (const int*)  d_in[3];
    float* out = (float*)d_out;

    float *qkv_p, *attn_p, *a_p, *w1_p, *w2_p;
    cudaGetSymbolAddress((void**)&qkv_p,  g_qkv);
    cudaGetSymbolAddress((void**)&attn_p, g_attn);
    cudaGetSymbolAddress((void**)&a_p,    g_a);
    cudaGetSymbolAddress((void**)&w1_p,   g_w1);
    cudaGetSymbolAddress((void**)&w2_p,   g_w2);

    const int mma_smem  = 65536;
    const int attn_smem = 98304;
    cudaFuncSetAttribute(mma_gemm_nt, cudaFuncAttributeMaxDynamicSharedMemorySize, mma_smem);
    cudaFuncSetAttribute(attn_kernel, cudaFuncAttributeMaxDynamicSharedMemorySize, attn_smem);

    // 0) pre-round inputs/weights to tf32 (rna)
    cvt_tf32<<<(TOTAL * DIMM / 4 + 255) / 256, 256>>>(hs,   a_p,  TOTAL * DIMM / 4);
    cvt_tf32<<<(NQKV * DIMM / 4 + 255) / 256, 256>>>(wqkv, w1_p, NQKV * DIMM / 4);
    cvt_tf32<<<(DIMM * DIMM / 4 + 255) / 256, 256>>>(wo,   w2_p, DIMM * DIMM / 4);

    // 1) QKV projection
    mma_gemm_nt<<<dim3(NQKV / 128, TOTAL / 128), 256, mma_smem>>>(
        a_p, w1_p, qkv_p, TOTAL, NQKV, DIMM, 1);
    // 2) RoPE (rounds q,k to tf32)
    rope_kernel<<<(TOTAL * 2 * NH * 32) / 256, 256>>>(cu);
    // 3) attention (prefetch-pipelined)
    attn_kernel<<<dim3(TOTAL / 128, NH), 256, attn_smem>>>(cu);
    // 4) output projection
    mma_gemm_nt<<<dim3(DIMM / 128, TOTAL / 128), 256, mma_smem>>>(
        attn_p, w2_p, out, TOTAL, DIMM, DIMM, 0);
}

// round 13
// speedup vs baseline: 1.3490x; 1.1039x over previous
#include <cuda_runtime.h>
#include <math.h>
#include <stdint.h>

#define TOTAL   5120
#define DIMM    1024
#define NH      16
#define HDD     64
#define NB      4
#define MAXLEN  2048
#define NQKV    3072

// Scratch (device globals: no allocation allowed)
__device__ float g_qkv[(size_t)TOTAL * NQKV];    // q|k|v (tf32 values)
__device__ float g_attn[(size_t)TOTAL * DIMM];   // attention out (tf32 values)
__device__ float g_a [(size_t)TOTAL * DIMM];     // hs rounded to tf32
__device__ float g_w1[(size_t)NQKV * DIMM];      // Wqkv rounded to tf32
__device__ float g_w2[(size_t)DIMM * DIMM];      // Wo rounded to tf32

extern __shared__ __align__(1024) uint8_t dynraw[];

__device__ __forceinline__ unsigned tf32r(float x) {
    unsigned u;
    asm("cvt.rna.tf32.f32 %0, %1;" : "=r"(u) : "f"(x));
    return u;
}
__device__ __forceinline__ float tf32rf(float x) {
    return __uint_as_float(tf32r(x));
}
__device__ __forceinline__ float ex2f(float x) {
    float r;
    asm("ex2.approx.f32 %0, %1;" : "=f"(r) : "f"(x));
    return r;
}

#define MMA_TF32(acc, a0,a1,a2,a3, b0,b1)                                     \
    asm volatile("mma.sync.aligned.m16n8k8.row.col.f32.tf32.tf32.f32 "        \
                 "{%0,%1,%2,%3}, {%4,%5,%6,%7}, {%8,%9}, {%0,%1,%2,%3};"      \
                 : "+f"((acc)[0]), "+f"((acc)[1]), "+f"((acc)[2]), "+f"((acc)[3]) \
                 : "r"(a0), "r"(a1), "r"(a2), "r"(a3), "r"(b0), "r"(b1))

// ---------------------------------------------------------------------------
// Elementwise round-to-tf32 copy (vectorized).
// ---------------------------------------------------------------------------
__global__ void __launch_bounds__(256) cvt_tf32(const float* __restrict__ src,
                                                float* __restrict__ dst, int n4)
{
    int i = blockIdx.x * 256 + threadIdx.x;
    if (i >= n4) return;
    float4 v = ((const float4*)src)[i];
    v.x = tf32rf(v.x); v.y = tf32rf(v.y);
    v.z = tf32rf(v.z); v.w = tf32rf(v.w);
    ((float4*)dst)[i] = v;
}

// ===========================================================================
// Proven 2-stage 128x128 mma.sync tf32 GEMM NT (occ 2, 64KB smem).
// ===========================================================================
__global__ void __launch_bounds__(256, 2) mma_gemm_nt(
    const float* __restrict__ A, const float* __restrict__ Bw,
    float* __restrict__ C, int M, int N, int K, int round_out)
{
    float* As = (float*)dynraw;                  // [2][128*32]
    float* Bs = (float*)dynraw + 8192;

    const int tid  = threadIdx.x;
    const int lane = tid & 31, w = tid >> 5;
    const int g = lane >> 2, t = lane & 3;
    const int wm = w >> 2, wn = w & 3;
    const int bm = blockIdx.y * 128, bn = blockIdx.x * 128;

    float acc[4][4][4] = {};

    const unsigned sA0 = (unsigned)__cvta_generic_to_shared(As);
    const unsigned sB0 = (unsigned)__cvta_generic_to_shared(Bs);

#define GEMM_STAGE(buf, k0)                                                   \
    {                                                                         \
        unsigned sa = sA0 + (buf) * 16384, sb = sB0 + (buf) * 16384;          \
        _Pragma("unroll")                                                     \
        for (int it = 0; it < 4; it++) {                                      \
            int id = tid + 256 * it;                                          \
            int row = id >> 3, c = id & 7;                                    \
            unsigned off = (unsigned)(row * 32 + ((c ^ (row & 7)) << 2)) * 4; \
            asm volatile("cp.async.ca.shared.global [%0],[%1],16;\n"          \
                         :: "r"(sa + off), "l"(&A [(size_t)(bm + row) * K + (k0) + c * 4])); \
            asm volatile("cp.async.ca.shared.global [%0],[%1],16;\n"          \
                         :: "r"(sb + off), "l"(&Bw[(size_t)(bn + row) * K + (k0) + c * 4])); \
        }                                                                     \
        asm volatile("cp.async.commit_group;\n");                             \
    }

    GEMM_STAGE(0, 0);
    int buf = 0;
    for (int k0 = 0; k0 < K; k0 += 32) {
        asm volatile("cp.async.wait_group 0;\n");
        __syncthreads();
        if (k0 + 32 < K) GEMM_STAGE(buf ^ 1, k0 + 32);

        const float* Ab = As + buf * 4096;
        const float* Bb = Bs + buf * 4096;
#pragma unroll
        for (int o = 0; o < 4; o++) {
            const int c0 = ((2 * o) ^ g) << 2, c1 = ((2 * o + 1) ^ g) << 2;
            unsigned a[4][4], b[4][2];
#pragma unroll
            for (int mt = 0; mt < 4; mt++) {
                int r0 = wm * 64 + mt * 16 + g;
                a[mt][0] = __float_as_uint(Ab[ r0      * 32 + c0 + t]);
                a[mt][2] = __float_as_uint(Ab[ r0      * 32 + c1 + t]);
                a[mt][1] = __float_as_uint(Ab[(r0 + 8) * 32 + c0 + t]);
                a[mt][3] = __float_as_uint(Ab[(r0 + 8) * 32 + c1 + t]);
            }
#pragma unroll
            for (int nt = 0; nt < 4; nt++) {
                int r0 = wn * 32 + nt * 8 + g;
                b[nt][0] = __float_as_uint(Bb[r0 * 32 + c0 + t]);
                b[nt][1] = __float_as_uint(Bb[r0 * 32 + c1 + t]);
            }
#pragma unroll
            for (int mt = 0; mt < 4; mt++)
#pragma unroll
                for (int nt = 0; nt < 4; nt++)
                    MMA_TF32(acc[mt][nt], a[mt][0], a[mt][1], a[mt][2], a[mt][3],
                             b[nt][0], b[nt][1]);
        }
        buf ^= 1;
    }

#pragma unroll
    for (int mt = 0; mt < 4; mt++) {
        int r = bm + wm * 64 + mt * 16 + g;
#pragma unroll
        for (int nt = 0; nt < 4; nt++) {
            int cn = bn + wn * 32 + nt * 8 + 2 * t;
            float v0 = acc[mt][nt][0], v1 = acc[mt][nt][1];
            float v2 = acc[mt][nt][2], v3 = acc[mt][nt][3];
            if (round_out) {
                v0 = tf32rf(v0); v1 = tf32rf(v1); v2 = tf32rf(v2); v3 = tf32rf(v3);
            }
            *(float2*)&C[(size_t)r * N + cn]       = make_float2(v0, v1);
            *(float2*)&C[(size_t)(r + 8) * N + cn] = make_float2(v2, v3);
        }
    }
}

// ---------------------------------------------------------------------------
// RoPE in-place on q,k sections of g_qkv; outputs rounded to tf32.
// ---------------------------------------------------------------------------
__global__ void __launch_bounds__(256) rope_kernel(const int* __restrict__ cu)
{
    int tt = blockIdx.x * 256 + threadIdx.x;
    int j  = tt & 31;
    int hh = (tt >> 5) & 15;
    int s  = (tt >> 9) & 1;
    int r  = tt >> 10;
    if (r >= TOTAL) return;

    int b = 0;
#pragma unroll
    for (int i = 1; i < NB; i++) if (r >= cu[i]) b = i;
    int pos = r - cu[b];

    float inv = exp2f(-(float)j * (13.287712379549449f / 32.0f));
    float fr  = (float)pos * inv;
    float c, sn;
    sincosf(fr, &sn, &c);

    float* base = g_qkv + (size_t)r * NQKV + s * DIMM + hh * HDD;
    float x1 = base[j], x2 = base[j + 32];
    base[j]      = tf32rf(x1 * c - x2 * sn);
    base[j + 32] = tf32rf(x2 * c + x1 * sn);
}

// ---------------------------------------------------------------------------
// Tensor-core flash attention (tf32, mma.sync), prefetch-pipelined.
// V stored at row stride 72 floats (72 mod 32 = 8): PV B-fragment banks are
// 8*((t+j)&3)+g — a bijection over the warp => conflict-free (fixes the
// 2-way conflict of the swizzled layout). Softmax in base-2 (ex2.approx);
// log2(e) folded into the Q scale (tf32-rounded).
// ---------------------------------------------------------------------------
__global__ void __launch_bounds__(256, 2) attn_kernel(const int* __restrict__ cu)
{
    float* Qs = (float*)dynraw;              // 128*64  (swizzled chunks)
    float* Ks = (float*)dynraw + 8192;       // 64*64   (swizzled chunks)
    float* Vs = (float*)dynraw + 12288;      // 64*72   (stride-72, linear)
    float* Ps = (float*)dynraw + 16896;      // 128*64  (swizzled chunks)

    const int tid  = threadIdx.x;
    const int lane = tid & 31, w = tid >> 5;
    const int g = lane >> 2, t = lane & 3;
    const int h  = blockIdx.y;
    const int qt = blockIdx.x * 128;

    const unsigned sK = (unsigned)__cvta_generic_to_shared(Ks);
    const unsigned sV = (unsigned)__cvta_generic_to_shared(Vs);

    int b = 0;
#pragma unroll
    for (int i = 1; i < NB; i++) if (qt >= cu[i]) b = i;
    const int base = cu[b];
    const int L    = cu[b + 1] - base;
    const int nkt  = L >> 6;

#define STAGE_K(j)                                                            \
    {                                                                         \
        if ((j) < nkt) {                                                      \
            const size_t kr0 = (size_t)(base + (j) * 64);                     \
            _Pragma("unroll")                                                 \
            for (int it = 0; it < 4; it++) {                                  \
                int id = tid + 256 * it;                                      \
                int row = id >> 4, c = id & 15;                               \
                unsigned off = (unsigned)(row * 64 + ((c ^ (row & 7)) << 2)) * 4; \
                asm volatile("cp.async.ca.shared.global [%0],[%1],16;\n"      \
                    :: "r"(sK + off),                                         \
                       "l"(&g_qkv[(kr0 + row) * NQKV + h * HDD + c * 4 + DIMM])); \
            }                                                                 \
        }                                                                     \
        asm volatile("cp.async.commit_group;\n");                             \
    }
#define STAGE_V(j)                                                            \
    {                                                                         \
        if ((j) < nkt) {                                                      \
            const size_t kr0 = (size_t)(base + (j) * 64);                     \
            _Pragma("unroll")                                                 \
            for (int it = 0; it < 4; it++) {                                  \
                int id = tid + 256 * it;                                      \
                int row = id >> 4, c = id & 15;                               \
                unsigned off = (unsigned)(row * 72 + c * 4) * 4;              \
                asm volatile("cp.async.ca.shared.global [%0],[%1],16;\n"      \
                    :: "r"(sV + off),                                         \
                       "l"(&g_qkv[(kr0 + row) * NQKV + h * HDD + c * 4 + 2 * DIMM])); \
            }                                                                 \
        }                                                                     \
        asm volatile("cp.async.commit_group;\n");                             \
    }

    // Q scale = (1/8) * log2(e); scores computed in log2 domain.
    const float QSCALE = 0.18033688011112042f;
#pragma unroll
    for (int it = 0; it < 8; it++) {
        int id = tid + 256 * it;
        int row = id >> 4, c = id & 15;
        float4 v = *(const float4*)&g_qkv[(size_t)(qt + row) * NQKV + h * HDD + c * 4];
        float* d = &Qs[row * 64 + ((c ^ (row & 7)) << 2)];
        d[0] = tf32rf(v.x * QSCALE); d[1] = tf32rf(v.y * QSCALE);
        d[2] = tf32rf(v.z * QSCALE); d[3] = tf32rf(v.w * QSCALE);
    }
    STAGE_K(0);
    STAGE_V(0);

    const int r0l = w * 16 + g;
    float m0 = -1e30f, m1 = -1e30f, l0 = 0.f, l1 = 0.f;
    float o_[8][4] = {};

    for (int kt = 0; kt < nkt; kt++) {
        asm volatile("cp.async.wait_group 1;\n");   // K(kt) done; V in flight
        __syncthreads();

        // ---- S = Q K^T (log2-domain scores) ----
        float s[8][4] = {};
#pragma unroll
        for (int o = 0; o < 8; o++) {
            const int c0 = ((2 * o) ^ g) << 2, c1 = ((2 * o + 1) ^ g) << 2;
            unsigned a0 = __float_as_uint(Qs[ r0l      * 64 + c0 + t]);
            unsigned a2 = __float_as_uint(Qs[ r0l      * 64 + c1 + t]);
            unsigned a1 = __float_as_uint(Qs[(r0l + 8) * 64 + c0 + t]);
            unsigned a3 = __float_as_uint(Qs[(r0l + 8) * 64 + c1 + t]);
#pragma unroll
            for (int j = 0; j < 8; j++) {
                int rb = j * 8 + g;
                unsigned b0 = __float_as_uint(Ks[rb * 64 + c0 + t]);
                unsigned b1 = __float_as_uint(Ks[rb * 64 + c1 + t]);
                MMA_TF32(s[j], a0, a1, a2, a3, b0, b1);
            }
        }

        // ---- online softmax (base 2) ----
        float rm0 = -1e30f, rm1 = -1e30f;
#pragma unroll
        for (int j = 0; j < 8; j++) {
            rm0 = fmaxf(rm0, fmaxf(s[j][0], s[j][1]));
            rm1 = fmaxf(rm1, fmaxf(s[j][2], s[j][3]));
        }
#pragma unroll
        for (int off = 1; off < 4; off <<= 1) {
            rm0 = fmaxf(rm0, __shfl_xor_sync(0xffffffffu, rm0, off));
            rm1 = fmaxf(rm1, __shfl_xor_sync(0xffffffffu, rm1, off));
        }
        float mn0 = fmaxf(m0, rm0), mn1 = fmaxf(m1, rm1);
        float f0 = ex2f(m0 - mn0), f1 = ex2f(m1 - mn1);
        float rs0 = 0.f, rs1 = 0.f;
#pragma unroll
        for (int j = 0; j < 8; j++) {
            s[j][0] = ex2f(s[j][0] - mn0); rs0 += s[j][0];
            s[j][1] = ex2f(s[j][1] - mn0); rs0 += s[j][1];
            s[j][2] = ex2f(s[j][2] - mn1); rs1 += s[j][2];
            s[j][3] = ex2f(s[j][3] - mn1); rs1 += s[j][3];
        }
#pragma unroll
        for (int off = 1; off < 4; off <<= 1) {
            rs0 += __shfl_xor_sync(0xffffffffu, rs0, off);
            rs1 += __shfl_xor_sync(0xffffffffu, rs1, off);
        }
        l0 = l0 * f0 + rs0;  m0 = mn0;
        l1 = l1 * f1 + rs1;  m1 = mn1;
#pragma unroll
        for (int j = 0; j < 8; j++) {
            o_[j][0] *= f0; o_[j][1] *= f0;
            o_[j][2] *= f1; o_[j][3] *= f1;
        }

        // ---- P -> warp-local swizzled smem ----
#pragma unroll
        for (int j = 0; j < 8; j++) {
            int ch = 2 * j + (t >> 1);
            int wd = 2 * (t & 1);
            float* p0 = &Ps[ r0l      * 64 + ((ch ^ g) << 2) + wd];
            p0[0] = tf32rf(s[j][0]);
            p0[1] = tf32rf(s[j][1]);
            float* p1 = &Ps[(r0l + 8) * 64 + ((ch ^ g) << 2) + wd];
            p1[0] = tf32rf(s[j][2]);
            p1[1] = tf32rf(s[j][3]);
        }
        __syncwarp();

        // ---- V(kt) ready; barrier doubles as "all K reads done" ----
        asm volatile("cp.async.wait_group 0;\n");
        __syncthreads();

        // ---- prefetch K(kt+1) (overlaps PV) ----
        STAGE_K(kt + 1);

        // ---- O += P V  (V: stride-72, conflict-free) ----
#pragma unroll
        for (int o = 0; o < 8; o++) {
            const int c0 = ((2 * o) ^ g) << 2, c1 = ((2 * o + 1) ^ g) << 2;
            unsigned a0 = __float_as_uint(Ps[ r0l      * 64 + c0 + t]);
            unsigned a2 = __float_as_uint(Ps[ r0l      * 64 + c1 + t]);
            unsigned a1 = __float_as_uint(Ps[(r0l + 8) * 64 + c0 + t]);
            unsigned a3 = __float_as_uint(Ps[(r0l + 8) * 64 + c1 + t]);
            const int kr  = 8 * o + t;
            const int kr2 = kr + 4;
#pragma unroll
            for (int j = 0; j < 8; j++) {
                unsigned b0 = __float_as_uint(Vs[kr  * 72 + j * 8 + g]);
                unsigned b1 = __float_as_uint(Vs[kr2 * 72 + j * 8 + g]);
                MMA_TF32(o_[j], a0, a1, a2, a3, b0, b1);
            }
        }
        __syncwarp();                            // P reads done (warp-local)

        __syncthreads();                         // all V reads done
        STAGE_V(kt + 1);                         // overlaps next QK^T+softmax
    }

    // epilogue (base 2): fold padded keys, normalize, store tf32-rounded
    const float npad = (float)(MAXLEN - L);
    float mf0 = (npad > 0.f) ? fmaxf(m0, 0.f) : m0;
    float mf1 = (npad > 0.f) ? fmaxf(m1, 0.f) : m1;
    float sc0 = ex2f(m0 - mf0), sc1 = ex2f(m1 - mf1);
    float w0 = sc0 / (l0 * sc0 + npad * ex2f(-mf0));
    float w1 = sc1 / (l1 * sc1 + npad * ex2f(-mf1));

    const int row0 = qt + r0l, row1 = row0 + 8;
#pragma unroll
    for (int j = 0; j < 8; j++) {
        int cn = h * HDD + j * 8 + 2 * t;
        *(float2*)&g_attn[(size_t)row0 * DIMM + cn] = make_float2(
            tf32rf(o_[j][0] * w0), tf32rf(o_[j][1] * w0));
        *(float2*)&g_attn[(size_t)row1 * DIMM + cn] = make_float2(
            tf32rf(o_[j][2] * w1), tf32rf(o_[j][3] * w1));
    }
}

// ---------------------------------------------------------------------------
extern "C" void kernel_launch(void* const* d_in, const int* in_sizes, int n_in,
                              void* d_out, int out_size)
{
    const float* hs   = (const float*)d_in[0];
    const float* wqkv = (const float*)d_in[1];
    const float* wo   = (const float*)d_in[2];
    const int*   cu   = (const int*)  d_in[3];
    float* out = (float*)d_out;

    float *qkv_p, *attn_p, *a_p, *w1_p, *w2_p;
    cudaGetSymbolAddress((void**)&qkv_p,  g_qkv);
    cudaGetSymbolAddress((void**)&attn_p, g_attn);
    cudaGetSymbolAddress((void**)&a_p,    g_a);
    cudaGetSymbolAddress((void**)&w1_p,   g_w1);
    cudaGetSymbolAddress((void**)&w2_p,   g_w2);

    const int mma_smem  = 65536;
    const int attn_smem = 100352;   // Q 32K + K 16K + V 18K + P 32K + pad
    cudaFuncSetAttribute(mma_gemm_nt, cudaFuncAttributeMaxDynamicSharedMemorySize, mma_smem);
    cudaFuncSetAttribute(attn_kernel, cudaFuncAttributeMaxDynamicSharedMemorySize, attn_smem);

    // 0) pre-round inputs/weights to tf32 (rna)
    cvt_tf32<<<(TOTAL * DIMM / 4 + 255) / 256, 256>>>(hs,   a_p,  TOTAL * DIMM / 4);
    cvt_tf32<<<(NQKV * DIMM / 4 + 255) / 256, 256>>>(wqkv, w1_p, NQKV * DIMM / 4);
    cvt_tf32<<<(DIMM * DIMM / 4 + 255) / 256, 256>>>(wo,   w2_p, DIMM * DIMM / 4);

    // 1) QKV projection
    mma_gemm_nt<<<dim3(NQKV / 128, TOTAL / 128), 256, mma_smem>>>(
        a_p, w1_p, qkv_p, TOTAL, NQKV, DIMM, 1);
    // 2) RoPE (rounds q,k to tf32)
    rope_kernel<<<(TOTAL * 2 * NH * 32) / 256, 256>>>(cu);
    // 3) attention (prefetch-pipelined, conflict-free V, base-2 softmax)
    attn_kernel<<<dim3(TOTAL / 128, NH), 256, attn_smem>>>(cu);
    // 4) output projection
    mma_gemm_nt<<<dim3(DIMM / 128, TOTAL / 128), 256, mma_smem>>>(
        attn_p, w2_p, out, TOTAL, DIMM, DIMM, 0);
}

// round 14
// speedup vs baseline: 1.4460x; 1.0719x over previous
#include <cuda_runtime.h>
#include <math.h>
#include <stdint.h>

#define TOTAL   5120
#define DIMM    1024
#define NH      16
#define HDD     64
#define NB      4
#define MAXLEN  2048
#define NQKV    3072

// Scratch (device globals: no allocation allowed)
__device__ float g_qkv[(size_t)TOTAL * NQKV];    // q|k|v (tf32 values)
__device__ float g_attn[(size_t)TOTAL * DIMM];   // attention out (tf32 values)
__device__ float g_a [(size_t)TOTAL * DIMM];     // hs rounded to tf32
__device__ float g_w1[(size_t)NQKV * DIMM];      // Wqkv rounded to tf32
__device__ float g_w2[(size_t)DIMM * DIMM];      // Wo rounded to tf32

extern __shared__ __align__(1024) uint8_t dynraw[];

__device__ __forceinline__ unsigned tf32r(float x) {
    unsigned u;
    asm("cvt.rna.tf32.f32 %0, %1;" : "=r"(u) : "f"(x));
    return u;
}
__device__ __forceinline__ float tf32rf(float x) {
    return __uint_as_float(tf32r(x));
}
__device__ __forceinline__ float ex2f(float x) {
    float r;
    asm("ex2.approx.f32 %0, %1;" : "=f"(r) : "f"(x));
    return r;
}

#define MMA_TF32(acc, a0,a1,a2,a3, b0,b1)                                     \
    asm volatile("mma.sync.aligned.m16n8k8.row.col.f32.tf32.tf32.f32 "        \
                 "{%0,%1,%2,%3}, {%4,%5,%6,%7}, {%8,%9}, {%0,%1,%2,%3};"      \
                 : "+f"((acc)[0]), "+f"((acc)[1]), "+f"((acc)[2]), "+f"((acc)[3]) \
                 : "r"(a0), "r"(a1), "r"(a2), "r"(a3), "r"(b0), "r"(b1))

// ---------------------------------------------------------------------------
// Elementwise round-to-tf32 copy (vectorized).
// ---------------------------------------------------------------------------
__global__ void __launch_bounds__(256) cvt_tf32(const float* __restrict__ src,
                                                float* __restrict__ dst, int n4)
{
    int i = blockIdx.x * 256 + threadIdx.x;
    if (i >= n4) return;
    float4 v = ((const float4*)src)[i];
    v.x = tf32rf(v.x); v.y = tf32rf(v.y);
    v.z = tf32rf(v.z); v.w = tf32rf(v.w);
    ((float4*)dst)[i] = v;
}

// ===========================================================================
// Proven 2-stage 128x128 mma.sync tf32 GEMM NT (occ 2, 64KB smem).
// ===========================================================================
__global__ void __launch_bounds__(256, 2) mma_gemm_nt(
    const float* __restrict__ A, const float* __restrict__ Bw,
    float* __restrict__ C, int M, int N, int K, int round_out)
{
    float* As = (float*)dynraw;                  // [2][128*32]
    float* Bs = (float*)dynraw + 8192;

    const int tid  = threadIdx.x;
    const int lane = tid & 31, w = tid >> 5;
    const int g = lane >> 2, t = lane & 3;
    const int wm = w >> 2, wn = w & 3;
    const int bm = blockIdx.y * 128, bn = blockIdx.x * 128;

    float acc[4][4][4] = {};

    const unsigned sA0 = (unsigned)__cvta_generic_to_shared(As);
    const unsigned sB0 = (unsigned)__cvta_generic_to_shared(Bs);

#define GEMM_STAGE(buf, k0)                                                   \
    {                                                                         \
        unsigned sa = sA0 + (buf) * 16384, sb = sB0 + (buf) * 16384;          \
        _Pragma("unroll")                                                     \
        for (int it = 0; it < 4; it++) {                                      \
            int id = tid + 256 * it;                                          \
            int row = id >> 3, c = id & 7;                                    \
            unsigned off = (unsigned)(row * 32 + ((c ^ (row & 7)) << 2)) * 4; \
            asm volatile("cp.async.ca.shared.global [%0],[%1],16;\n"          \
                         :: "r"(sa + off), "l"(&A [(size_t)(bm + row) * K + (k0) + c * 4])); \
            asm volatile("cp.async.ca.shared.global [%0],[%1],16;\n"          \
                         :: "r"(sb + off), "l"(&Bw[(size_t)(bn + row) * K + (k0) + c * 4])); \
        }                                                                     \
        asm volatile("cp.async.commit_group;\n");                             \
    }

    GEMM_STAGE(0, 0);
    int buf = 0;
    for (int k0 = 0; k0 < K; k0 += 32) {
        asm volatile("cp.async.wait_group 0;\n");
        __syncthreads();
        if (k0 + 32 < K) GEMM_STAGE(buf ^ 1, k0 + 32);

        const float* Ab = As + buf * 4096;
        const float* Bb = Bs + buf * 4096;
#pragma unroll
        for (int o = 0; o < 4; o++) {
            const int c0 = ((2 * o) ^ g) << 2, c1 = ((2 * o + 1) ^ g) << 2;
            unsigned a[4][4], b[4][2];
#pragma unroll
            for (int mt = 0; mt < 4; mt++) {
                int r0 = wm * 64 + mt * 16 + g;
                a[mt][0] = __float_as_uint(Ab[ r0      * 32 + c0 + t]);
                a[mt][2] = __float_as_uint(Ab[ r0      * 32 + c1 + t]);
                a[mt][1] = __float_as_uint(Ab[(r0 + 8) * 32 + c0 + t]);
                a[mt][3] = __float_as_uint(Ab[(r0 + 8) * 32 + c1 + t]);
            }
#pragma unroll
            for (int nt = 0; nt < 4; nt++) {
                int r0 = wn * 32 + nt * 8 + g;
                b[nt][0] = __float_as_uint(Bb[r0 * 32 + c0 + t]);
                b[nt][1] = __float_as_uint(Bb[r0 * 32 + c1 + t]);
            }
#pragma unroll
            for (int mt = 0; mt < 4; mt++)
#pragma unroll
                for (int nt = 0; nt < 4; nt++)
                    MMA_TF32(acc[mt][nt], a[mt][0], a[mt][1], a[mt][2], a[mt][3],
                             b[nt][0], b[nt][1]);
        }
        buf ^= 1;
    }

#pragma unroll
    for (int mt = 0; mt < 4; mt++) {
        int r = bm + wm * 64 + mt * 16 + g;
#pragma unroll
        for (int nt = 0; nt < 4; nt++) {
            int cn = bn + wn * 32 + nt * 8 + 2 * t;
            float v0 = acc[mt][nt][0], v1 = acc[mt][nt][1];
            float v2 = acc[mt][nt][2], v3 = acc[mt][nt][3];
            if (round_out) {
                v0 = tf32rf(v0); v1 = tf32rf(v1); v2 = tf32rf(v2); v3 = tf32rf(v3);
            }
            *(float2*)&C[(size_t)r * N + cn]       = make_float2(v0, v1);
            *(float2*)&C[(size_t)(r + 8) * N + cn] = make_float2(v2, v3);
        }
    }
}

// ---------------------------------------------------------------------------
// RoPE in-place on q,k sections of g_qkv; outputs rounded to tf32.
// ---------------------------------------------------------------------------
__global__ void __launch_bounds__(256) rope_kernel(const int* __restrict__ cu)
{
    int tt = blockIdx.x * 256 + threadIdx.x;
    int j  = tt & 31;
    int hh = (tt >> 5) & 15;
    int s  = (tt >> 9) & 1;
    int r  = tt >> 10;
    if (r >= TOTAL) return;

    int b = 0;
#pragma unroll
    for (int i = 1; i < NB; i++) if (r >= cu[i]) b = i;
    int pos = r - cu[b];

    float inv = exp2f(-(float)j * (13.287712379549449f / 32.0f));
    float fr  = (float)pos * inv;
    float c, sn;
    sincosf(fr, &sn, &c);

    float* base = g_qkv + (size_t)r * NQKV + s * DIMM + hh * HDD;
    float x1 = base[j], x2 = base[j + 32];
    base[j]      = tf32rf(x1 * c - x2 * sn);
    base[j + 32] = tf32rf(x2 * c + x1 * sn);
}

// ---------------------------------------------------------------------------
// Tensor-core flash attention (tf32, mma.sync), prefetch-pipelined.
// 4 warps x 32 q-rows per warp (two m16 tiles): K/V B-fragment duplication
// drops from 8x to 4x => crossbar-bound -> tensor-bound. 128 threads, occ 2.
// V stride-72 (conflict-free PV), base-2 softmax, log2(e) folded into Q.
// ---------------------------------------------------------------------------
__global__ void __launch_bounds__(128, 2) attn_kernel(const int* __restrict__ cu)
{
    float* Qs = (float*)dynraw;              // 128*64  (swizzled chunks)
    float* Ks = (float*)dynraw + 8192;       // 64*64   (swizzled chunks)
    float* Vs = (float*)dynraw + 12288;      // 64*72   (stride-72, linear)
    float* Ps = (float*)dynraw + 16896;      // 128*64  (swizzled chunks)

    const int tid  = threadIdx.x;
    const int lane = tid & 31, w = tid >> 5;   // 4 warps
    const int g = lane >> 2, t = lane & 3;
    const int h  = blockIdx.y;
    const int qt = blockIdx.x * 128;

    const unsigned sK = (unsigned)__cvta_generic_to_shared(Ks);
    const unsigned sV = (unsigned)__cvta_generic_to_shared(Vs);

    int b = 0;
#pragma unroll
    for (int i = 1; i < NB; i++) if (qt >= cu[i]) b = i;
    const int base = cu[b];
    const int L    = cu[b + 1] - base;
    const int nkt  = L >> 6;

#define STAGE_K(j)                                                            \
    {                                                                         \
        if ((j) < nkt) {                                                      \
            const size_t kr0 = (size_t)(base + (j) * 64);                     \
            _Pragma("unroll")                                                 \
            for (int it = 0; it < 8; it++) {                                  \
                int id = tid + 128 * it;                                      \
                int row = id >> 4, c = id & 15;                               \
                unsigned off = (unsigned)(row * 64 + ((c ^ (row & 7)) << 2)) * 4; \
                asm volatile("cp.async.ca.shared.global [%0],[%1],16;\n"      \
                    :: "r"(sK + off),                                         \
                       "l"(&g_qkv[(kr0 + row) * NQKV + h * HDD + c * 4 + DIMM])); \
            }                                                                 \
        }                                                                     \
        asm volatile("cp.async.commit_group;\n");                             \
    }
#define STAGE_V(j)                                                            \
    {                                                                         \
        if ((j) < nkt) {                                                      \
            const size_t kr0 = (size_t)(base + (j) * 64);                     \
            _Pragma("unroll")                                                 \
            for (int it = 0; it < 8; it++) {                                  \
                int id = tid + 128 * it;                                      \
                int row = id >> 4, c = id & 15;                               \
                unsigned off = (unsigned)(row * 72 + c * 4) * 4;              \
                asm volatile("cp.async.ca.shared.global [%0],[%1],16;\n"      \
                    :: "r"(sV + off),                                         \
                       "l"(&g_qkv[(kr0 + row) * NQKV + h * HDD + c * 4 + 2 * DIMM])); \
            }                                                                 \
        }                                                                     \
        asm volatile("cp.async.commit_group;\n");                             \
    }

    // Q scale = (1/8) * log2(e); scores computed in log2 domain.
    const float QSCALE = 0.18033688011112042f;
#pragma unroll
    for (int it = 0; it < 16; it++) {
        int id = tid + 128 * it;
        int row = id >> 4, c = id & 15;
        float4 v = *(const float4*)&g_qkv[(size_t)(qt + row) * NQKV + h * HDD + c * 4];
        float* d = &Qs[row * 64 + ((c ^ (row & 7)) << 2)];
        d[0] = tf32rf(v.x * QSCALE); d[1] = tf32rf(v.y * QSCALE);
        d[2] = tf32rf(v.z * QSCALE); d[3] = tf32rf(v.w * QSCALE);
    }
    STAGE_K(0);
    STAGE_V(0);

    // warp covers q rows [w*32, w*32+32): m-tiles at rows rw0 and rw0+16
    const int rw0 = w * 32;
    float m_[2][2], l_[2][2];
#pragma unroll
    for (int mt = 0; mt < 2; mt++) {
        m_[mt][0] = -1e30f; m_[mt][1] = -1e30f;
        l_[mt][0] = 0.f;    l_[mt][1] = 0.f;
    }
    float o_[2][8][4] = {};

    for (int kt = 0; kt < nkt; kt++) {
        asm volatile("cp.async.wait_group 1;\n");   // K(kt) done; V in flight
        __syncthreads();

        // ---- S = Q K^T (log2-domain scores) ----
        float s[2][8][4] = {};
#pragma unroll
        for (int o = 0; o < 8; o++) {
            const int c0 = ((2 * o) ^ g) << 2, c1 = ((2 * o + 1) ^ g) << 2;
            unsigned a[2][4];
#pragma unroll
            for (int mt = 0; mt < 2; mt++) {
                int r0 = rw0 + mt * 16 + g;
                a[mt][0] = __float_as_uint(Qs[ r0      * 64 + c0 + t]);
                a[mt][2] = __float_as_uint(Qs[ r0      * 64 + c1 + t]);
                a[mt][1] = __float_as_uint(Qs[(r0 + 8) * 64 + c0 + t]);
                a[mt][3] = __float_as_uint(Qs[(r0 + 8) * 64 + c1 + t]);
            }
#pragma unroll
            for (int j = 0; j < 8; j++) {
                int rb = j * 8 + g;
                unsigned b0 = __float_as_uint(Ks[rb * 64 + c0 + t]);
                unsigned b1 = __float_as_uint(Ks[rb * 64 + c1 + t]);
#pragma unroll
                for (int mt = 0; mt < 2; mt++)
                    MMA_TF32(s[mt][j], a[mt][0], a[mt][1], a[mt][2], a[mt][3], b0, b1);
            }
        }

        // ---- online softmax (base 2), two m-tiles ----
#pragma unroll
        for (int mt = 0; mt < 2; mt++) {
            float rm0 = -1e30f, rm1 = -1e30f;
#pragma unroll
            for (int j = 0; j < 8; j++) {
                rm0 = fmaxf(rm0, fmaxf(s[mt][j][0], s[mt][j][1]));
                rm1 = fmaxf(rm1, fmaxf(s[mt][j][2], s[mt][j][3]));
            }
#pragma unroll
            for (int off = 1; off < 4; off <<= 1) {
                rm0 = fmaxf(rm0, __shfl_xor_sync(0xffffffffu, rm0, off));
                rm1 = fmaxf(rm1, __shfl_xor_sync(0xffffffffu, rm1, off));
            }
            float mn0 = fmaxf(m_[mt][0], rm0), mn1 = fmaxf(m_[mt][1], rm1);
            float f0 = ex2f(m_[mt][0] - mn0), f1 = ex2f(m_[mt][1] - mn1);
            float rs0 = 0.f, rs1 = 0.f;
#pragma unroll
            for (int j = 0; j < 8; j++) {
                s[mt][j][0] = ex2f(s[mt][j][0] - mn0); rs0 += s[mt][j][0];
                s[mt][j][1] = ex2f(s[mt][j][1] - mn0); rs0 += s[mt][j][1];
                s[mt][j][2] = ex2f(s[mt][j][2] - mn1); rs1 += s[mt][j][2];
                s[mt][j][3] = ex2f(s[mt][j][3] - mn1); rs1 += s[mt][j][3];
            }
#pragma unroll
            for (int off = 1; off < 4; off <<= 1) {
                rs0 += __shfl_xor_sync(0xffffffffu, rs0, off);
                rs1 += __shfl_xor_sync(0xffffffffu, rs1, off);
            }
            l_[mt][0] = l_[mt][0] * f0 + rs0;  m_[mt][0] = mn0;
            l_[mt][1] = l_[mt][1] * f1 + rs1;  m_[mt][1] = mn1;
#pragma unroll
            for (int j = 0; j < 8; j++) {
                o_[mt][j][0] *= f0; o_[mt][j][1] *= f0;
                o_[mt][j][2] *= f1; o_[mt][j][3] *= f1;
            }

            // ---- P -> warp-local swizzled smem ----
#pragma unroll
            for (int j = 0; j < 8; j++) {
                int ch = 2 * j + (t >> 1);
                int wd = 2 * (t & 1);
                int r0 = rw0 + mt * 16 + g;
                float* p0 = &Ps[ r0      * 64 + ((ch ^ g) << 2) + wd];
                p0[0] = tf32rf(s[mt][j][0]);
                p0[1] = tf32rf(s[mt][j][1]);
                float* p1 = &Ps[(r0 + 8) * 64 + ((ch ^ g) << 2) + wd];
                p1[0] = tf32rf(s[mt][j][2]);
                p1[1] = tf32rf(s[mt][j][3]);
            }
        }
        __syncwarp();

        // ---- V(kt) ready; barrier doubles as "all K reads done" ----
        asm volatile("cp.async.wait_group 0;\n");
        __syncthreads();

        // ---- prefetch K(kt+1) (overlaps PV) ----
        STAGE_K(kt + 1);

        // ---- O += P V  (V: stride-72, conflict-free) ----
#pragma unroll
        for (int o = 0; o < 8; o++) {
            const int c0 = ((2 * o) ^ g) << 2, c1 = ((2 * o + 1) ^ g) << 2;
            unsigned a[2][4];
#pragma unroll
            for (int mt = 0; mt < 2; mt++) {
                int r0 = rw0 + mt * 16 + g;
                a[mt][0] = __float_as_uint(Ps[ r0      * 64 + c0 + t]);
                a[mt][2] = __float_as_uint(Ps[ r0      * 64 + c1 + t]);
                a[mt][1] = __float_as_uint(Ps[(r0 + 8) * 64 + c0 + t]);
                a[mt][3] = __float_as_uint(Ps[(r0 + 8) * 64 + c1 + t]);
            }
            const int kr  = 8 * o + t;
            const int kr2 = kr + 4;
#pragma unroll
            for (int j = 0; j < 8; j++) {
                unsigned b0 = __float_as_uint(Vs[kr  * 72 + j * 8 + g]);
                unsigned b1 = __float_as_uint(Vs[kr2 * 72 + j * 8 + g]);
#pragma unroll
                for (int mt = 0; mt < 2; mt++)
                    MMA_TF32(o_[mt][j], a[mt][0], a[mt][1], a[mt][2], a[mt][3], b0, b1);
            }
        }
        __syncwarp();                            // P reads done (warp-local)

        __syncthreads();                         // all V reads done
        STAGE_V(kt + 1);                         // overlaps next QK^T+softmax
    }

    // epilogue (base 2): fold padded keys, normalize, store tf32-rounded
    const float npad = (float)(MAXLEN - L);
#pragma unroll
    for (int mt = 0; mt < 2; mt++) {
        float mf0 = (npad > 0.f) ? fmaxf(m_[mt][0], 0.f) : m_[mt][0];
        float mf1 = (npad > 0.f) ? fmaxf(m_[mt][1], 0.f) : m_[mt][1];
        float sc0 = ex2f(m_[mt][0] - mf0), sc1 = ex2f(m_[mt][1] - mf1);
        float w0 = sc0 / (l_[mt][0] * sc0 + npad * ex2f(-mf0));
        float w1 = sc1 / (l_[mt][1] * sc1 + npad * ex2f(-mf1));

        const int row0 = qt + rw0 + mt * 16 + g, row1 = row0 + 8;
#pragma unroll
        for (int j = 0; j < 8; j++) {
            int cn = h * HDD + j * 8 + 2 * t;
            *(float2*)&g_attn[(size_t)row0 * DIMM + cn] = make_float2(
                tf32rf(o_[mt][j][0] * w0), tf32rf(o_[mt][j][1] * w0));
            *(float2*)&g_attn[(size_t)row1 * DIMM + cn] = make_float2(
                tf32rf(o_[mt][j][2] * w1), tf32rf(o_[mt][j][3] * w1));
        }
    }
}

// ---------------------------------------------------------------------------
extern "C" void kernel_launch(void* const* d_in, const int* in_sizes, int n_in,
                              void* d_out, int out_size)
{
    const float* hs   = (const float*)d_in[0];
    const float* wqkv = (const float*)d_in[1];
    const float* wo   = (const float*)d_in[2];
    const int*   cu   = (const int*)  d_in[3];
    float* out = (float*)d_out;

    float *qkv_p, *attn_p, *a_p, *w1_p, *w2_p;
    cudaGetSymbolAddress((void**)&qkv_p,  g_qkv);
    cudaGetSymbolAddress((void**)&attn_p, g_attn);
    cudaGetSymbolAddress((void**)&a_p,    g_a);
    cudaGetSymbolAddress((void**)&w1_p,   g_w1);
    cudaGetSymbolAddress((void**)&w2_p,   g_w2);

    const int mma_smem  = 65536;
    const int attn_smem = 100352;   // Q 32K + K 16K + V 18K + P 32K + pad
    cudaFuncSetAttribute(mma_gemm_nt, cudaFuncAttributeMaxDynamicSharedMemorySize, mma_smem);
    cudaFuncSetAttribute(attn_kernel, cudaFuncAttributeMaxDynamicSharedMemorySize, attn_smem);

    // 0) pre-round inputs/weights to tf32 (rna)
    cvt_tf32<<<(TOTAL * DIMM / 4 + 255) / 256, 256>>>(hs,   a_p,  TOTAL * DIMM / 4);
    cvt_tf32<<<(NQKV * DIMM / 4 + 255) / 256, 256>>>(wqkv, w1_p, NQKV * DIMM / 4);
    cvt_tf32<<<(DIMM * DIMM / 4 + 255) / 256, 256>>>(wo,   w2_p, DIMM * DIMM / 4);

    // 1) QKV projection
    mma_gemm_nt<<<dim3(NQKV / 128, TOTAL / 128), 256, mma_smem>>>(
        a_p, w1_p, qkv_p, TOTAL, NQKV, DIMM, 1);
    // 2) RoPE (rounds q,k to tf32)
    rope_kernel<<<(TOTAL * 2 * NH * 32) / 256, 256>>>(cu);
    // 3) attention (4-warp CTA: halved K/V fragment duplication)
    attn_kernel<<<dim3(TOTAL / 128, NH), 128, attn_smem>>>(cu);
    // 4) output projection
    mma_gemm_nt<<<dim3(DIMM / 128, TOTAL / 128), 256, mma_smem>>>(
        attn_p, w2_p, out, TOTAL, DIMM, DIMM, 0);
}

// round 15
// speedup vs baseline: 1.4798x; 1.0234x over previous
#include <cuda_runtime.h>
#include <math.h>
#include <stdint.h>

#define TOTAL   5120
#define DIMM    1024
#define NH      16
#define HDD     64
#define NB      4
#define MAXLEN  2048
#define NQKV    3072

// Scratch (device globals: no allocation allowed)
__device__ float g_qkv[(size_t)TOTAL * NQKV];    // q|k|v (tf32 values)
__device__ float g_attn[(size_t)TOTAL * DIMM];   // attention out (tf32 values)
__device__ float g_a [(size_t)TOTAL * DIMM];     // hs rounded to tf32
__device__ float g_w1[(size_t)NQKV * DIMM];      // Wqkv rounded to tf32
__device__ float g_w2[(size_t)DIMM * DIMM];      // Wo rounded to tf32

extern __shared__ __align__(1024) uint8_t dynraw[];

__device__ __forceinline__ unsigned tf32r(float x) {
    unsigned u;
    asm("cvt.rna.tf32.f32 %0, %1;" : "=r"(u) : "f"(x));
    return u;
}
__device__ __forceinline__ float tf32rf(float x) {
    return __uint_as_float(tf32r(x));
}
__device__ __forceinline__ float ex2f(float x) {
    float r;
    asm("ex2.approx.f32 %0, %1;" : "=f"(r) : "f"(x));
    return r;
}

#define MMA_TF32(acc, a0,a1,a2,a3, b0,b1)                                     \
    asm volatile("mma.sync.aligned.m16n8k8.row.col.f32.tf32.tf32.f32 "        \
                 "{%0,%1,%2,%3}, {%4,%5,%6,%7}, {%8,%9}, {%0,%1,%2,%3};"      \
                 : "+f"((acc)[0]), "+f"((acc)[1]), "+f"((acc)[2]), "+f"((acc)[3]) \
                 : "r"(a0), "r"(a1), "r"(a2), "r"(a3), "r"(b0), "r"(b1))

// ---------------------------------------------------------------------------
// Elementwise round-to-tf32 copy (vectorized).
// ---------------------------------------------------------------------------
__global__ void __launch_bounds__(256) cvt_tf32(const float* __restrict__ src,
                                                float* __restrict__ dst, int n4)
{
    int i = blockIdx.x * 256 + threadIdx.x;
    if (i >= n4) return;
    float4 v = ((const float4*)src)[i];
    v.x = tf32rf(v.x); v.y = tf32rf(v.y);
    v.z = tf32rf(v.z); v.w = tf32rf(v.w);
    ((float4*)dst)[i] = v;
}

// ===========================================================================
// GEMM v4: 128x128 CTA tile, 4 warps in 2x2 grid, warp tile 64x64
// (1.0 LDS per MMA, -33% crossbar vs 8-warp layout). 128 threads, 64KB smem,
// occ 2 (51K regs + 128KB smem per SM). cp.async double-buffered, chunk-XOR
// swizzle, inputs pre-rounded tf32.
// ===========================================================================
__global__ void __launch_bounds__(128, 2) mma_gemm_nt(
    const float* __restrict__ A, const float* __restrict__ Bw,
    float* __restrict__ C, int M, int N, int K, int round_out)
{
    float* As = (float*)dynraw;                  // [2][128*32]
    float* Bs = (float*)dynraw + 8192;

    const int tid  = threadIdx.x;
    const int lane = tid & 31, w = tid >> 5;     // 4 warps
    const int g = lane >> 2, t = lane & 3;
    const int wm = w >> 1, wn = w & 1;           // 2 x 2 warp grid
    const int bm = blockIdx.y * 128, bn = blockIdx.x * 128;

    float acc[4][8][4] = {};                     // 128 accumulator regs

    const unsigned sA0 = (unsigned)__cvta_generic_to_shared(As);
    const unsigned sB0 = (unsigned)__cvta_generic_to_shared(Bs);

#define GEMM_STAGE(buf, k0)                                                   \
    {                                                                         \
        unsigned sa = sA0 + (buf) * 16384, sb = sB0 + (buf) * 16384;          \
        _Pragma("unroll")                                                     \
        for (int it = 0; it < 8; it++) {                                      \
            int id = tid + 128 * it;                                          \
            int row = id >> 3, c = id & 7;                                    \
            unsigned off = (unsigned)(row * 32 + ((c ^ (row & 7)) << 2)) * 4; \
            asm volatile("cp.async.ca.shared.global [%0],[%1],16;\n"          \
                         :: "r"(sa + off), "l"(&A [(size_t)(bm + row) * K + (k0) + c * 4])); \
            asm volatile("cp.async.ca.shared.global [%0],[%1],16;\n"          \
                         :: "r"(sb + off), "l"(&Bw[(size_t)(bn + row) * K + (k0) + c * 4])); \
        }                                                                     \
        asm volatile("cp.async.commit_group;\n");                             \
    }

    GEMM_STAGE(0, 0);
    int buf = 0;
    for (int k0 = 0; k0 < K; k0 += 32) {
        asm volatile("cp.async.wait_group 0;\n");
        __syncthreads();
        if (k0 + 32 < K) GEMM_STAGE(buf ^ 1, k0 + 32);

        const float* Ab = As + buf * 4096;
        const float* Bb = Bs + buf * 4096;
#pragma unroll
        for (int o = 0; o < 4; o++) {
            const int c0 = ((2 * o) ^ g) << 2, c1 = ((2 * o + 1) ^ g) << 2;
            unsigned a[4][4], b[8][2];
#pragma unroll
            for (int mt = 0; mt < 4; mt++) {
                int r0 = wm * 64 + mt * 16 + g;
                a[mt][0] = __float_as_uint(Ab[ r0      * 32 + c0 + t]);
                a[mt][2] = __float_as_uint(Ab[ r0      * 32 + c1 + t]);
                a[mt][1] = __float_as_uint(Ab[(r0 + 8) * 32 + c0 + t]);
                a[mt][3] = __float_as_uint(Ab[(r0 + 8) * 32 + c1 + t]);
            }
#pragma unroll
            for (int nt = 0; nt < 8; nt++) {
                int rb = wn * 64 + nt * 8 + g;
                b[nt][0] = __float_as_uint(Bb[rb * 32 + c0 + t]);
                b[nt][1] = __float_as_uint(Bb[rb * 32 + c1 + t]);
            }
#pragma unroll
            for (int mt = 0; mt < 4; mt++)
#pragma unroll
                for (int nt = 0; nt < 8; nt++)
                    MMA_TF32(acc[mt][nt], a[mt][0], a[mt][1], a[mt][2], a[mt][3],
                             b[nt][0], b[nt][1]);
        }
        buf ^= 1;
    }

#pragma unroll
    for (int mt = 0; mt < 4; mt++) {
        int r = bm + wm * 64 + mt * 16 + g;
#pragma unroll
        for (int nt = 0; nt < 8; nt++) {
            int cn = bn + wn * 64 + nt * 8 + 2 * t;
            float v0 = acc[mt][nt][0], v1 = acc[mt][nt][1];
            float v2 = acc[mt][nt][2], v3 = acc[mt][nt][3];
            if (round_out) {
                v0 = tf32rf(v0); v1 = tf32rf(v1); v2 = tf32rf(v2); v3 = tf32rf(v3);
            }
            *(float2*)&C[(size_t)r * N + cn]       = make_float2(v0, v1);
            *(float2*)&C[(size_t)(r + 8) * N + cn] = make_float2(v2, v3);
        }
    }
}

// ---------------------------------------------------------------------------
// RoPE in-place on q,k sections of g_qkv; outputs rounded to tf32.
// ---------------------------------------------------------------------------
__global__ void __launch_bounds__(256) rope_kernel(const int* __restrict__ cu)
{
    int tt = blockIdx.x * 256 + threadIdx.x;
    int j  = tt & 31;
    int hh = (tt >> 5) & 15;
    int s  = (tt >> 9) & 1;
    int r  = tt >> 10;
    if (r >= TOTAL) return;

    int b = 0;
#pragma unroll
    for (int i = 1; i < NB; i++) if (r >= cu[i]) b = i;
    int pos = r - cu[b];

    float inv = exp2f(-(float)j * (13.287712379549449f / 32.0f));
    float fr  = (float)pos * inv;
    float c, sn;
    sincosf(fr, &sn, &c);

    float* base = g_qkv + (size_t)r * NQKV + s * DIMM + hh * HDD;
    float x1 = base[j], x2 = base[j + 32];
    base[j]      = tf32rf(x1 * c - x2 * sn);
    base[j + 32] = tf32rf(x2 * c + x1 * sn);
}

// ---------------------------------------------------------------------------
// Tensor-core flash attention (tf32, mma.sync), prefetch-pipelined.
// 4 warps x 32 q-rows per warp. V stride-72 (conflict-free PV), base-2
// softmax with log2(e) folded into Q. 128 threads, occ 2.
// ---------------------------------------------------------------------------
__global__ void __launch_bounds__(128, 2) attn_kernel(const int* __restrict__ cu)
{
    float* Qs = (float*)dynraw;              // 128*64  (swizzled chunks)
    float* Ks = (float*)dynraw + 8192;       // 64*64   (swizzled chunks)
    float* Vs = (float*)dynraw + 12288;      // 64*72   (stride-72, linear)
    float* Ps = (float*)dynraw + 16896;      // 128*64  (swizzled chunks)

    const int tid  = threadIdx.x;
    const int lane = tid & 31, w = tid >> 5;   // 4 warps
    const int g = lane >> 2, t = lane & 3;
    const int h  = blockIdx.y;
    const int qt = blockIdx.x * 128;

    const unsigned sK = (unsigned)__cvta_generic_to_shared(Ks);
    const unsigned sV = (unsigned)__cvta_generic_to_shared(Vs);

    int b = 0;
#pragma unroll
    for (int i = 1; i < NB; i++) if (qt >= cu[i]) b = i;
    const int base = cu[b];
    const int L    = cu[b + 1] - base;
    const int nkt  = L >> 6;

#define STAGE_K(j)                                                            \
    {                                                                         \
        if ((j) < nkt) {                                                      \
            const size_t kr0 = (size_t)(base + (j) * 64);                     \
            _Pragma("unroll")                                                 \
            for (int it = 0; it < 8; it++) {                                  \
                int id = tid + 128 * it;                                      \
                int row = id >> 4, c = id & 15;                               \
                unsigned off = (unsigned)(row * 64 + ((c ^ (row & 7)) << 2)) * 4; \
                asm volatile("cp.async.ca.shared.global [%0],[%1],16;\n"      \
                    :: "r"(sK + off),                                         \
                       "l"(&g_qkv[(kr0 + row) * NQKV + h * HDD + c * 4 + DIMM])); \
            }                                                                 \
        }                                                                     \
        asm volatile("cp.async.commit_group;\n");                             \
    }
#define STAGE_V(j)                                                            \
    {                                                                         \
        if ((j) < nkt) {                                                      \
            const size_t kr0 = (size_t)(base + (j) * 64);                     \
            _Pragma("unroll")                                                 \
            for (int it = 0; it < 8; it++) {                                  \
                int id = tid + 128 * it;                                      \
                int row = id >> 4, c = id & 15;                               \
                unsigned off = (unsigned)(row * 72 + c * 4) * 4;              \
                asm volatile("cp.async.ca.shared.global [%0],[%1],16;\n"      \
                    :: "r"(sV + off),                                         \
                       "l"(&g_qkv[(kr0 + row) * NQKV + h * HDD + c * 4 + 2 * DIMM])); \
            }                                                                 \
        }                                                                     \
        asm volatile("cp.async.commit_group;\n");                             \
    }

    // Q scale = (1/8) * log2(e); scores computed in log2 domain.
    const float QSCALE = 0.18033688011112042f;
#pragma unroll
    for (int it = 0; it < 16; it++) {
        int id = tid + 128 * it;
        int row = id >> 4, c = id & 15;
        float4 v = *(const float4*)&g_qkv[(size_t)(qt + row) * NQKV + h * HDD + c * 4];
        float* d = &Qs[row * 64 + ((c ^ (row & 7)) << 2)];
        d[0] = tf32rf(v.x * QSCALE); d[1] = tf32rf(v.y * QSCALE);
        d[2] = tf32rf(v.z * QSCALE); d[3] = tf32rf(v.w * QSCALE);
    }
    STAGE_K(0);
    STAGE_V(0);

    const int rw0 = w * 32;
    float m_[2][2], l_[2][2];
#pragma unroll
    for (int mt = 0; mt < 2; mt++) {
        m_[mt][0] = -1e30f; m_[mt][1] = -1e30f;
        l_[mt][0] = 0.f;    l_[mt][1] = 0.f;
    }
    float o_[2][8][4] = {};

    for (int kt = 0; kt < nkt; kt++) {
        asm volatile("cp.async.wait_group 1;\n");   // K(kt) done; V in flight
        __syncthreads();

        // ---- S = Q K^T (log2-domain scores) ----
        float s[2][8][4] = {};
#pragma unroll
        for (int o = 0; o < 8; o++) {
            const int c0 = ((2 * o) ^ g) << 2, c1 = ((2 * o + 1) ^ g) << 2;
            unsigned a[2][4];
#pragma unroll
            for (int mt = 0; mt < 2; mt++) {
                int r0 = rw0 + mt * 16 + g;
                a[mt][0] = __float_as_uint(Qs[ r0      * 64 + c0 + t]);
                a[mt][2] = __float_as_uint(Qs[ r0      * 64 + c1 + t]);
                a[mt][1] = __float_as_uint(Qs[(r0 + 8) * 64 + c0 + t]);
                a[mt][3] = __float_as_uint(Qs[(r0 + 8) * 64 + c1 + t]);
            }
#pragma unroll
            for (int j = 0; j < 8; j++) {
                int rb = j * 8 + g;
                unsigned b0 = __float_as_uint(Ks[rb * 64 + c0 + t]);
                unsigned b1 = __float_as_uint(Ks[rb * 64 + c1 + t]);
#pragma unroll
                for (int mt = 0; mt < 2; mt++)
                    MMA_TF32(s[mt][j], a[mt][0], a[mt][1], a[mt][2], a[mt][3], b0, b1);
            }
        }

        // ---- online softmax (base 2), two m-tiles ----
#pragma unroll
        for (int mt = 0; mt < 2; mt++) {
            float rm0 = -1e30f, rm1 = -1e30f;
#pragma unroll
            for (int j = 0; j < 8; j++) {
                rm0 = fmaxf(rm0, fmaxf(s[mt][j][0], s[mt][j][1]));
                rm1 = fmaxf(rm1, fmaxf(s[mt][j][2], s[mt][j][3]));
            }
#pragma unroll
            for (int off = 1; off < 4; off <<= 1) {
                rm0 = fmaxf(rm0, __shfl_xor_sync(0xffffffffu, rm0, off));
                rm1 = fmaxf(rm1, __shfl_xor_sync(0xffffffffu, rm1, off));
            }
            float mn0 = fmaxf(m_[mt][0], rm0), mn1 = fmaxf(m_[mt][1], rm1);
            float f0 = ex2f(m_[mt][0] - mn0), f1 = ex2f(m_[mt][1] - mn1);
            float rs0 = 0.f, rs1 = 0.f;
#pragma unroll
            for (int j = 0; j < 8; j++) {
                s[mt][j][0] = ex2f(s[mt][j][0] - mn0); rs0 += s[mt][j][0];
                s[mt][j][1] = ex2f(s[mt][j][1] - mn0); rs0 += s[mt][j][1];
                s[mt][j][2] = ex2f(s[mt][j][2] - mn1); rs1 += s[mt][j][2];
                s[mt][j][3] = ex2f(s[mt][j][3] - mn1); rs1 += s[mt][j][3];
            }
#pragma unroll
            for (int off = 1; off < 4; off <<= 1) {
                rs0 += __shfl_xor_sync(0xffffffffu, rs0, off);
                rs1 += __shfl_xor_sync(0xffffffffu, rs1, off);
            }
            l_[mt][0] = l_[mt][0] * f0 + rs0;  m_[mt][0] = mn0;
            l_[mt][1] = l_[mt][1] * f1 + rs1;  m_[mt][1] = mn1;
#pragma unroll
            for (int j = 0; j < 8; j++) {
                o_[mt][j][0] *= f0; o_[mt][j][1] *= f0;
                o_[mt][j][2] *= f1; o_[mt][j][3] *= f1;
            }

            // ---- P -> warp-local swizzled smem ----
#pragma unroll
            for (int j = 0; j < 8; j++) {
                int ch = 2 * j + (t >> 1);
                int wd = 2 * (t & 1);
                int r0 = rw0 + mt * 16 + g;
                float* p0 = &Ps[ r0      * 64 + ((ch ^ g) << 2) + wd];
                p0[0] = tf32rf(s[mt][j][0]);
                p0[1] = tf32rf(s[mt][j][1]);
                float* p1 = &Ps[(r0 + 8) * 64 + ((ch ^ g) << 2) + wd];
                p1[0] = tf32rf(s[mt][j][2]);
                p1[1] = tf32rf(s[mt][j][3]);
            }
        }
        __syncwarp();

        // ---- V(kt) ready; barrier doubles as "all K reads done" ----
        asm volatile("cp.async.wait_group 0;\n");
        __syncthreads();

        // ---- prefetch K(kt+1) (overlaps PV) ----
        STAGE_K(kt + 1);

        // ---- O += P V  (V: stride-72, conflict-free) ----
#pragma unroll
        for (int o = 0; o < 8; o++) {
            const int c0 = ((2 * o) ^ g) << 2, c1 = ((2 * o + 1) ^ g) << 2;
            unsigned a[2][4];
#pragma unroll
            for (int mt = 0; mt < 2; mt++) {
                int r0 = rw0 + mt * 16 + g;
                a[mt][0] = __float_as_uint(Ps[ r0      * 64 + c0 + t]);
                a[mt][2] = __float_as_uint(Ps[ r0      * 64 + c1 + t]);
                a[mt][1] = __float_as_uint(Ps[(r0 + 8) * 64 + c0 + t]);
                a[mt][3] = __float_as_uint(Ps[(r0 + 8) * 64 + c1 + t]);
            }
            const int kr  = 8 * o + t;
            const int kr2 = kr + 4;
#pragma unroll
            for (int j = 0; j < 8; j++) {
                unsigned b0 = __float_as_uint(Vs[kr  * 72 + j * 8 + g]);
                unsigned b1 = __float_as_uint(Vs[kr2 * 72 + j * 8 + g]);
#pragma unroll
                for (int mt = 0; mt < 2; mt++)
                    MMA_TF32(o_[mt][j], a[mt][0], a[mt][1], a[mt][2], a[mt][3], b0, b1);
            }
        }
        __syncwarp();                            // P reads done (warp-local)

        __syncthreads();                         // all V reads done
        STAGE_V(kt + 1);                         // overlaps next QK^T+softmax
    }

    // epilogue (base 2): fold padded keys, normalize, store tf32-rounded
    const float npad = (float)(MAXLEN - L);
#pragma unroll
    for (int mt = 0; mt < 2; mt++) {
        float mf0 = (npad > 0.f) ? fmaxf(m_[mt][0], 0.f) : m_[mt][0];
        float mf1 = (npad > 0.f) ? fmaxf(m_[mt][1], 0.f) : m_[mt][1];
        float sc0 = ex2f(m_[mt][0] - mf0), sc1 = ex2f(m_[mt][1] - mf1);
        float w0 = sc0 / (l_[mt][0] * sc0 + npad * ex2f(-mf0));
        float w1 = sc1 / (l_[mt][1] * sc1 + npad * ex2f(-mf1));

        const int row0 = qt + rw0 + mt * 16 + g, row1 = row0 + 8;
#pragma unroll
        for (int j = 0; j < 8; j++) {
            int cn = h * HDD + j * 8 + 2 * t;
            *(float2*)&g_attn[(size_t)row0 * DIMM + cn] = make_float2(
                tf32rf(o_[mt][j][0] * w0), tf32rf(o_[mt][j][1] * w0));
            *(float2*)&g_attn[(size_t)row1 * DIMM + cn] = make_float2(
                tf32rf(o_[mt][j][2] * w1), tf32rf(o_[mt][j][3] * w1));
        }
    }
}

// ---------------------------------------------------------------------------
extern "C" void kernel_launch(void* const* d_in, const int* in_sizes, int n_in,
                              void* d_out, int out_size)
{
    const float* hs   = (const float*)d_in[0];
    const float* wqkv = (const float*)d_in[1];
    const float* wo   = (const float*)d_in[2];
    const int*   cu   = (const int*)  d_in[3];
    float* out = (float*)d_out;

    float *qkv_p, *attn_p, *a_p, *w1_p, *w2_p;
    cudaGetSymbolAddress((void**)&qkv_p,  g_qkv);
    cudaGetSymbolAddress((void**)&attn_p, g_attn);
    cudaGetSymbolAddress((void**)&a_p,    g_a);
    cudaGetSymbolAddress((void**)&w1_p,   g_w1);
    cudaGetSymbolAddress((void**)&w2_p,   g_w2);

    const int mma_smem  = 65536;
    const int attn_smem = 100352;
    cudaFuncSetAttribute(mma_gemm_nt, cudaFuncAttributeMaxDynamicSharedMemorySize, mma_smem);
    cudaFuncSetAttribute(attn_kernel, cudaFuncAttributeMaxDynamicSharedMemorySize, attn_smem);

    // 0) pre-round inputs/weights to tf32 (rna)
    cvt_tf32<<<(TOTAL * DIMM / 4 + 255) / 256, 256>>>(hs,   a_p,  TOTAL * DIMM / 4);
    cvt_tf32<<<(NQKV * DIMM / 4 + 255) / 256, 256>>>(wqkv, w1_p, NQKV * DIMM / 4);
    cvt_tf32<<<(DIMM * DIMM / 4 + 255) / 256, 256>>>(wo,   w2_p, DIMM * DIMM / 4);

    // 1) QKV projection (4-warp GEMM, 1.0 LDS/MMA)
    mma_gemm_nt<<<dim3(NQKV / 128, TOTAL / 128), 128, mma_smem>>>(
        a_p, w1_p, qkv_p, TOTAL, NQKV, DIMM, 1);
    // 2) RoPE (rounds q,k to tf32)
    rope_kernel<<<(TOTAL * 2 * NH * 32) / 256, 256>>>(cu);
    // 3) attention (4-warp CTA, conflict-free V, base-2 softmax)
    attn_kernel<<<dim3(TOTAL / 128, NH), 128, attn_smem>>>(cu);
    // 4) output projection
    mma_gemm_nt<<<dim3(DIMM / 128, TOTAL / 128), 128, mma_smem>>>(
        attn_p, w2_p, out, TOTAL, DIMM, DIMM, 0);
}

// round 16
// speedup vs baseline: 1.5180x; 1.0258x over previous
#include <cuda_runtime.h>
#include <math.h>
#include <stdint.h>

#define TOTAL   5120
#define DIMM    1024
#define NH      16
#define HDD     64
#define NB      4
#define MAXLEN  2048
#define NQKV    3072

// Scratch (device globals: no allocation allowed)
__device__ float g_qkv[(size_t)TOTAL * NQKV];    // q|k|v (tf32 values)
__device__ float g_attn[(size_t)TOTAL * DIMM];   // attention out (tf32 values)
__device__ float g_a [(size_t)TOTAL * DIMM];     // hs rounded to tf32
__device__ float g_w1[(size_t)NQKV * DIMM];      // Wqkv rounded to tf32
__device__ float g_w2[(size_t)DIMM * DIMM];      // Wo rounded to tf32

extern __shared__ __align__(1024) uint8_t dynraw[];

__device__ __forceinline__ unsigned tf32r(float x) {
    unsigned u;
    asm("cvt.rna.tf32.f32 %0, %1;" : "=r"(u) : "f"(x));
    return u;
}
__device__ __forceinline__ float tf32rf(float x) {
    return __uint_as_float(tf32r(x));
}
__device__ __forceinline__ float ex2f(float x) {
    float r;
    asm("ex2.approx.f32 %0, %1;" : "=f"(r) : "f"(x));
    return r;
}

#define MMA_TF32(acc, a0,a1,a2,a3, b0,b1)                                     \
    asm volatile("mma.sync.aligned.m16n8k8.row.col.f32.tf32.tf32.f32 "        \
                 "{%0,%1,%2,%3}, {%4,%5,%6,%7}, {%8,%9}, {%0,%1,%2,%3};"      \
                 : "+f"((acc)[0]), "+f"((acc)[1]), "+f"((acc)[2]), "+f"((acc)[3]) \
                 : "r"(a0), "r"(a1), "r"(a2), "r"(a3), "r"(b0), "r"(b1))

// ---------------------------------------------------------------------------
// Elementwise round-to-tf32 copy (vectorized).
// ---------------------------------------------------------------------------
__global__ void __launch_bounds__(256) cvt_tf32(const float* __restrict__ src,
                                                float* __restrict__ dst, int n4)
{
    int i = blockIdx.x * 256 + threadIdx.x;
    if (i >= n4) return;
    float4 v = ((const float4*)src)[i];
    v.x = tf32rf(v.x); v.y = tf32rf(v.y);
    v.z = tf32rf(v.z); v.w = tf32rf(v.w);
    ((float4*)dst)[i] = v;
}

// ===========================================================================
// GEMM (frozen): 128x128 CTA tile, 4 warps (2x2), warp tile 64x64,
// cp.async double-buffered, chunk-XOR swizzle, inputs pre-rounded tf32.
// ===========================================================================
__global__ void __launch_bounds__(128, 2) mma_gemm_nt(
    const float* __restrict__ A, const float* __restrict__ Bw,
    float* __restrict__ C, int M, int N, int K, int round_out)
{
    float* As = (float*)dynraw;                  // [2][128*32]
    float* Bs = (float*)dynraw + 8192;

    const int tid  = threadIdx.x;
    const int lane = tid & 31, w = tid >> 5;     // 4 warps
    const int g = lane >> 2, t = lane & 3;
    const int wm = w >> 1, wn = w & 1;           // 2 x 2 warp grid
    const int bm = blockIdx.y * 128, bn = blockIdx.x * 128;

    float acc[4][8][4] = {};

    const unsigned sA0 = (unsigned)__cvta_generic_to_shared(As);
    const unsigned sB0 = (unsigned)__cvta_generic_to_shared(Bs);

#define GEMM_STAGE(buf, k0)                                                   \
    {                                                                         \
        unsigned sa = sA0 + (buf) * 16384, sb = sB0 + (buf) * 16384;          \
        _Pragma("unroll")                                                     \
        for (int it = 0; it < 8; it++) {                                      \
            int id = tid + 128 * it;                                          \
            int row = id >> 3, c = id & 7;                                    \
            unsigned off = (unsigned)(row * 32 + ((c ^ (row & 7)) << 2)) * 4; \
            asm volatile("cp.async.ca.shared.global [%0],[%1],16;\n"          \
                         :: "r"(sa + off), "l"(&A [(size_t)(bm + row) * K + (k0) + c * 4])); \
            asm volatile("cp.async.ca.shared.global [%0],[%1],16;\n"          \
                         :: "r"(sb + off), "l"(&Bw[(size_t)(bn + row) * K + (k0) + c * 4])); \
        }                                                                     \
        asm volatile("cp.async.commit_group;\n");                             \
    }

    GEMM_STAGE(0, 0);
    int buf = 0;
    for (int k0 = 0; k0 < K; k0 += 32) {
        asm volatile("cp.async.wait_group 0;\n");
        __syncthreads();
        if (k0 + 32 < K) GEMM_STAGE(buf ^ 1, k0 + 32);

        const float* Ab = As + buf * 4096;
        const float* Bb = Bs + buf * 4096;
#pragma unroll
        for (int o = 0; o < 4; o++) {
            const int c0 = ((2 * o) ^ g) << 2, c1 = ((2 * o + 1) ^ g) << 2;
            unsigned a[4][4], b[8][2];
#pragma unroll
            for (int mt = 0; mt < 4; mt++) {
                int r0 = wm * 64 + mt * 16 + g;
                a[mt][0] = __float_as_uint(Ab[ r0      * 32 + c0 + t]);
                a[mt][2] = __float_as_uint(Ab[ r0      * 32 + c1 + t]);
                a[mt][1] = __float_as_uint(Ab[(r0 + 8) * 32 + c0 + t]);
                a[mt][3] = __float_as_uint(Ab[(r0 + 8) * 32 + c1 + t]);
            }
#pragma unroll
            for (int nt = 0; nt < 8; nt++) {
                int rb = wn * 64 + nt * 8 + g;
                b[nt][0] = __float_as_uint(Bb[rb * 32 + c0 + t]);
                b[nt][1] = __float_as_uint(Bb[rb * 32 + c1 + t]);
            }
#pragma unroll
            for (int mt = 0; mt < 4; mt++)
#pragma unroll
                for (int nt = 0; nt < 8; nt++)
                    MMA_TF32(acc[mt][nt], a[mt][0], a[mt][1], a[mt][2], a[mt][3],
                             b[nt][0], b[nt][1]);
        }
        buf ^= 1;
    }

#pragma unroll
    for (int mt = 0; mt < 4; mt++) {
        int r = bm + wm * 64 + mt * 16 + g;
#pragma unroll
        for (int nt = 0; nt < 8; nt++) {
            int cn = bn + wn * 64 + nt * 8 + 2 * t;
            float v0 = acc[mt][nt][0], v1 = acc[mt][nt][1];
            float v2 = acc[mt][nt][2], v3 = acc[mt][nt][3];
            if (round_out) {
                v0 = tf32rf(v0); v1 = tf32rf(v1); v2 = tf32rf(v2); v3 = tf32rf(v3);
            }
            *(float2*)&C[(size_t)r * N + cn]       = make_float2(v0, v1);
            *(float2*)&C[(size_t)(r + 8) * N + cn] = make_float2(v2, v3);
        }
    }
}

// ---------------------------------------------------------------------------
// RoPE in-place on q,k sections of g_qkv; outputs rounded to tf32.
// ---------------------------------------------------------------------------
__global__ void __launch_bounds__(256) rope_kernel(const int* __restrict__ cu)
{
    int tt = blockIdx.x * 256 + threadIdx.x;
    int j  = tt & 31;
    int hh = (tt >> 5) & 15;
    int s  = (tt >> 9) & 1;
    int r  = tt >> 10;
    if (r >= TOTAL) return;

    int b = 0;
#pragma unroll
    for (int i = 1; i < NB; i++) if (r >= cu[i]) b = i;
    int pos = r - cu[b];

    float inv = exp2f(-(float)j * (13.287712379549449f / 32.0f));
    float fr  = (float)pos * inv;
    float c, sn;
    sincosf(fr, &sn, &c);

    float* base = g_qkv + (size_t)r * NQKV + s * DIMM + hh * HDD;
    float x1 = base[j], x2 = base[j + 32];
    base[j]      = tf32rf(x1 * c - x2 * sn);
    base[j + 32] = tf32rf(x2 * c + x1 * sn);
}

// ---------------------------------------------------------------------------
// Tensor-core flash attention (tf32, mma.sync), prefetch-pipelined.
// Q FRAGMENTS REGISTER-RESIDENT: staged once through the Ps buffer, loaded
// into qf[8][2][4], never re-read from smem (-64 LDS/warp/tile, -32KB smem).
// 4 warps x 32 q-rows; V stride-72 (conflict-free); base-2 softmax.
// ---------------------------------------------------------------------------
__global__ void __launch_bounds__(128, 2) attn_kernel(const int* __restrict__ cu)
{
    float* Ks = (float*)dynraw;              // 64*64  swizzled   (16 KB)
    float* Vs = (float*)dynraw + 4096;       // 64*72  stride-72  (18 KB)
    float* Ps = (float*)dynraw + 8704;       // 128*64 swizzled   (32 KB)

    const int tid  = threadIdx.x;
    const int lane = tid & 31, w = tid >> 5;   // 4 warps
    const int g = lane >> 2, t = lane & 3;
    const int h  = blockIdx.y;
    const int qt = blockIdx.x * 128;

    const unsigned sK = (unsigned)__cvta_generic_to_shared(Ks);
    const unsigned sV = (unsigned)__cvta_generic_to_shared(Vs);

    int b = 0;
#pragma unroll
    for (int i = 1; i < NB; i++) if (qt >= cu[i]) b = i;
    const int base = cu[b];
    const int L    = cu[b + 1] - base;
    const int nkt  = L >> 6;

#define STAGE_K(j)                                                            \
    {                                                                         \
        if ((j) < nkt) {                                                      \
            const size_t kr0 = (size_t)(base + (j) * 64);                     \
            _Pragma("unroll")                                                 \
            for (int it = 0; it < 8; it++) {                                  \
                int id = tid + 128 * it;                                      \
                int row = id >> 4, c = id & 15;                               \
                unsigned off = (unsigned)(row * 64 + ((c ^ (row & 7)) << 2)) * 4; \
                asm volatile("cp.async.ca.shared.global [%0],[%1],16;\n"      \
                    :: "r"(sK + off),                                         \
                       "l"(&g_qkv[(kr0 + row) * NQKV + h * HDD + c * 4 + DIMM])); \
            }                                                                 \
        }                                                                     \
        asm volatile("cp.async.commit_group;\n");                             \
    }
#define STAGE_V(j)                                                            \
    {                                                                         \
        if ((j) < nkt) {                                                      \
            const size_t kr0 = (size_t)(base + (j) * 64);                     \
            _Pragma("unroll")                                                 \
            for (int it = 0; it < 8; it++) {                                  \
                int id = tid + 128 * it;                                      \
                int row = id >> 4, c = id & 15;                               \
                unsigned off = (unsigned)(row * 72 + c * 4) * 4;              \
                asm volatile("cp.async.ca.shared.global [%0],[%1],16;\n"      \
                    :: "r"(sV + off),                                         \
                       "l"(&g_qkv[(kr0 + row) * NQKV + h * HDD + c * 4 + 2 * DIMM])); \
            }                                                                 \
        }                                                                     \
        asm volatile("cp.async.commit_group;\n");                             \
    }

    // kick off K0/V0 loads first (independent of Ps)
    STAGE_K(0);
    STAGE_V(0);

    // stage Q through Ps (scaled by (1/8)*log2(e), tf32-rounded)
    const float QSCALE = 0.18033688011112042f;
#pragma unroll
    for (int it = 0; it < 16; it++) {
        int id = tid + 128 * it;
        int row = id >> 4, c = id & 15;
        float4 v = *(const float4*)&g_qkv[(size_t)(qt + row) * NQKV + h * HDD + c * 4];
        float* d = &Ps[row * 64 + ((c ^ (row & 7)) << 2)];
        d[0] = tf32rf(v.x * QSCALE); d[1] = tf32rf(v.y * QSCALE);
        d[2] = tf32rf(v.z * QSCALE); d[3] = tf32rf(v.w * QSCALE);
    }
    __syncthreads();

    // load Q fragments into registers (warp-local rows of Ps; Ps is
    // overwritten later only by this warp's own P rows)
    const int rw0 = w * 32;
    unsigned qf[8][2][4];
#pragma unroll
    for (int o = 0; o < 8; o++) {
        const int c0 = ((2 * o) ^ g) << 2, c1 = ((2 * o + 1) ^ g) << 2;
#pragma unroll
        for (int mt = 0; mt < 2; mt++) {
            int r0 = rw0 + mt * 16 + g;
            qf[o][mt][0] = __float_as_uint(Ps[ r0      * 64 + c0 + t]);
            qf[o][mt][2] = __float_as_uint(Ps[ r0      * 64 + c1 + t]);
            qf[o][mt][1] = __float_as_uint(Ps[(r0 + 8) * 64 + c0 + t]);
            qf[o][mt][3] = __float_as_uint(Ps[(r0 + 8) * 64 + c1 + t]);
        }
    }

    float m_[2][2], l_[2][2];
#pragma unroll
    for (int mt = 0; mt < 2; mt++) {
        m_[mt][0] = -1e30f; m_[mt][1] = -1e30f;
        l_[mt][0] = 0.f;    l_[mt][1] = 0.f;
    }
    float o_[2][8][4] = {};

    for (int kt = 0; kt < nkt; kt++) {
        asm volatile("cp.async.wait_group 1;\n");   // K(kt) done; V in flight
        __syncthreads();

        // ---- S = Q K^T (Q from registers) ----
        float s[2][8][4] = {};
#pragma unroll
        for (int o = 0; o < 8; o++) {
            const int c0 = ((2 * o) ^ g) << 2, c1 = ((2 * o + 1) ^ g) << 2;
#pragma unroll
            for (int j = 0; j < 8; j++) {
                int rb = j * 8 + g;
                unsigned b0 = __float_as_uint(Ks[rb * 64 + c0 + t]);
                unsigned b1 = __float_as_uint(Ks[rb * 64 + c1 + t]);
#pragma unroll
                for (int mt = 0; mt < 2; mt++)
                    MMA_TF32(s[mt][j], qf[o][mt][0], qf[o][mt][1],
                             qf[o][mt][2], qf[o][mt][3], b0, b1);
            }
        }

        // ---- online softmax (base 2), two m-tiles ----
#pragma unroll
        for (int mt = 0; mt < 2; mt++) {
            float rm0 = -1e30f, rm1 = -1e30f;
#pragma unroll
            for (int j = 0; j < 8; j++) {
                rm0 = fmaxf(rm0, fmaxf(s[mt][j][0], s[mt][j][1]));
                rm1 = fmaxf(rm1, fmaxf(s[mt][j][2], s[mt][j][3]));
            }
#pragma unroll
            for (int off = 1; off < 4; off <<= 1) {
                rm0 = fmaxf(rm0, __shfl_xor_sync(0xffffffffu, rm0, off));
                rm1 = fmaxf(rm1, __shfl_xor_sync(0xffffffffu, rm1, off));
            }
            float mn0 = fmaxf(m_[mt][0], rm0), mn1 = fmaxf(m_[mt][1], rm1);
            float f0 = ex2f(m_[mt][0] - mn0), f1 = ex2f(m_[mt][1] - mn1);
            float rs0 = 0.f, rs1 = 0.f;
#pragma unroll
            for (int j = 0; j < 8; j++) {
                s[mt][j][0] = ex2f(s[mt][j][0] - mn0); rs0 += s[mt][j][0];
                s[mt][j][1] = ex2f(s[mt][j][1] - mn0); rs0 += s[mt][j][1];
                s[mt][j][2] = ex2f(s[mt][j][2] - mn1); rs1 += s[mt][j][2];
                s[mt][j][3] = ex2f(s[mt][j][3] - mn1); rs1 += s[mt][j][3];
            }
#pragma unroll
            for (int off = 1; off < 4; off <<= 1) {
                rs0 += __shfl_xor_sync(0xffffffffu, rs0, off);
                rs1 += __shfl_xor_sync(0xffffffffu, rs1, off);
            }
            l_[mt][0] = l_[mt][0] * f0 + rs0;  m_[mt][0] = mn0;
            l_[mt][1] = l_[mt][1] * f1 + rs1;  m_[mt][1] = mn1;
#pragma unroll
            for (int j = 0; j < 8; j++) {
                o_[mt][j][0] *= f0; o_[mt][j][1] *= f0;
                o_[mt][j][2] *= f1; o_[mt][j][3] *= f1;
            }

            // ---- P -> warp-local swizzled smem (own rows of Ps) ----
#pragma unroll
            for (int j = 0; j < 8; j++) {
                int ch = 2 * j + (t >> 1);
                int wd = 2 * (t & 1);
                int r0 = rw0 + mt * 16 + g;
                float* p0 = &Ps[ r0      * 64 + ((ch ^ g) << 2) + wd];
                p0[0] = tf32rf(s[mt][j][0]);
                p0[1] = tf32rf(s[mt][j][1]);
                float* p1 = &Ps[(r0 + 8) * 64 + ((ch ^ g) << 2) + wd];
                p1[0] = tf32rf(s[mt][j][2]);
                p1[1] = tf32rf(s[mt][j][3]);
            }
        }
        __syncwarp();

        // ---- V(kt) ready; barrier doubles as "all K reads done" ----
        asm volatile("cp.async.wait_group 0;\n");
        __syncthreads();

        // ---- prefetch K(kt+1) (overlaps PV) ----
        STAGE_K(kt + 1);

        // ---- O += P V  (V: stride-72, conflict-free) ----
#pragma unroll
        for (int o = 0; o < 8; o++) {
            const int c0 = ((2 * o) ^ g) << 2, c1 = ((2 * o + 1) ^ g) << 2;
            unsigned a[2][4];
#pragma unroll
            for (int mt = 0; mt < 2; mt++) {
                int r0 = rw0 + mt * 16 + g;
                a[mt][0] = __float_as_uint(Ps[ r0      * 64 + c0 + t]);
                a[mt][2] = __float_as_uint(Ps[ r0      * 64 + c1 + t]);
                a[mt][1] = __float_as_uint(Ps[(r0 + 8) * 64 + c0 + t]);
                a[mt][3] = __float_as_uint(Ps[(r0 + 8) * 64 + c1 + t]);
            }
            const int kr  = 8 * o + t;
            const int kr2 = kr + 4;
#pragma unroll
            for (int j = 0; j < 8; j++) {
                unsigned b0 = __float_as_uint(Vs[kr  * 72 + j * 8 + g]);
                unsigned b1 = __float_as_uint(Vs[kr2 * 72 + j * 8 + g]);
#pragma unroll
                for (int mt = 0; mt < 2; mt++)
                    MMA_TF32(o_[mt][j], a[mt][0], a[mt][1], a[mt][2], a[mt][3], b0, b1);
            }
        }
        __syncwarp();                            // P reads done (warp-local)

        __syncthreads();                         // all V reads done
        STAGE_V(kt + 1);                         // overlaps next QK^T+softmax
    }

    // epilogue (base 2): fold padded keys, normalize, store tf32-rounded
    const float npad = (float)(MAXLEN - L);
#pragma unroll
    for (int mt = 0; mt < 2; mt++) {
        float mf0 = (npad > 0.f) ? fmaxf(m_[mt][0], 0.f) : m_[mt][0];
        float mf1 = (npad > 0.f) ? fmaxf(m_[mt][1], 0.f) : m_[mt][1];
        float sc0 = ex2f(m_[mt][0] - mf0), sc1 = ex2f(m_[mt][1] - mf1);
        float w0 = sc0 / (l_[mt][0] * sc0 + npad * ex2f(-mf0));
        float w1 = sc1 / (l_[mt][1] * sc1 + npad * ex2f(-mf1));

        const int row0 = qt + rw0 + mt * 16 + g, row1 = row0 + 8;
#pragma unroll
        for (int j = 0; j < 8; j++) {
            int cn = h * HDD + j * 8 + 2 * t;
            *(float2*)&g_attn[(size_t)row0 * DIMM + cn] = make_float2(
                tf32rf(o_[mt][j][0] * w0), tf32rf(o_[mt][j][1] * w0));
            *(float2*)&g_attn[(size_t)row1 * DIMM + cn] = make_float2(
                tf32rf(o_[mt][j][2] * w1), tf32rf(o_[mt][j][3] * w1));
        }
    }
}

// ---------------------------------------------------------------------------
extern "C" void kernel_launch(void* const* d_in, const int* in_sizes, int n_in,
                              void* d_out, int out_size)
{
    const float* hs   = (const float*)d_in[0];
    const float* wqkv = (const float*)d_in[1];
    const float* wo   = (const float*)d_in[2];
    const int*   cu   = (const int*)  d_in[3];
    float* out = (float*)d_out;

    float *qkv_p, *attn_p, *a_p, *w1_p, *w2_p;
    cudaGetSymbolAddress((void**)&qkv_p,  g_qkv);
    cudaGetSymbolAddress((void**)&attn_p, g_attn);
    cudaGetSymbolAddress((void**)&a_p,    g_a);
    cudaGetSymbolAddress((void**)&w1_p,   g_w1);
    cudaGetSymbolAddress((void**)&w2_p,   g_w2);

    const int mma_smem  = 65536;
    const int attn_smem = 69632;   // K 16K + V 18K + P 32K + pad
    cudaFuncSetAttribute(mma_gemm_nt, cudaFuncAttributeMaxDynamicSharedMemorySize, mma_smem);
    cudaFuncSetAttribute(attn_kernel, cudaFuncAttributeMaxDynamicSharedMemorySize, attn_smem);

    // 0) pre-round inputs/weights to tf32 (rna)
    cvt_tf32<<<(TOTAL * DIMM / 4 + 255) / 256, 256>>>(hs,   a_p,  TOTAL * DIMM / 4);
    cvt_tf32<<<(NQKV * DIMM / 4 + 255) / 256, 256>>>(wqkv, w1_p, NQKV * DIMM / 4);
    cvt_tf32<<<(DIMM * DIMM / 4 + 255) / 256, 256>>>(wo,   w2_p, DIMM * DIMM / 4);

    // 1) QKV projection
    mma_gemm_nt<<<dim3(NQKV / 128, TOTAL / 128), 128, mma_smem>>>(
        a_p, w1_p, qkv_p, TOTAL, NQKV, DIMM, 1);
    // 2) RoPE (rounds q,k to tf32)
    rope_kernel<<<(TOTAL * 2 * NH * 32) / 256, 256>>>(cu);
    // 3) attention (register-resident Q fragments)
    attn_kernel<<<dim3(TOTAL / 128, NH), 128, attn_smem>>>(cu);
    // 4) output projection
    mma_gemm_nt<<<dim3(DIMM / 128, TOTAL / 128), 128, mma_smem>>>(
        attn_p, w2_p, out, TOTAL, DIMM, DIMM, 0);
}